// round 7
// baseline (speedup 1.0000x reference)
#include <cuda_runtime.h>
#include <cuda_bf16.h>
#include <math.h>
#include <stdint.h>

#define TPB   256
#define PTS   128
#define NBLK  2048

// ---------------- smem layout (bytes) ----------------
#define SM_ENCH 0u            // enc hi: 128 pts x 128B (64 bf16: enc[0..62], bias)
#define SM_ENCL 16384u        // enc lo
#define SM_WHI  32768u        // weight hi region (49152 max)
#define SM_WLO  81920u        // weight lo region
#define SM_CHEB 131072u       // 128 x 68B
#define SM_TOTAL 139776u

// ---------------- global weight scratch (pre-swizzled smem images) ----------------
#define IMG_L0  0u
#define P_L0    16384u        // 64 rows x 256B
#define P_HID   49152u        // 192 rows x 256B
#define IMG_HID(l) (32768u + (uint32_t)((l) - 1) * 98304u)   // l = 1..5
#define IMG_OUT 524288u
#define P_OUT   16384u        // 128 rows x 128B (N padded to 64)
__device__ __align__(16) unsigned char g_wscratch[557056];

// ---------------- PTX helpers ----------------
__device__ __forceinline__ uint32_t smem_u32(const void* p) {
    uint32_t a;
    asm("{ .reg .u64 t; cvta.to.shared.u64 t, %1; cvt.u32.u64 %0, t; }" : "=r"(a) : "l"(p));
    return a;
}
__device__ __forceinline__ void ldsm_x4(uint32_t& r0, uint32_t& r1, uint32_t& r2, uint32_t& r3, uint32_t a) {
    asm volatile("ldmatrix.sync.aligned.m8n8.x4.shared.b16 {%0,%1,%2,%3}, [%4];"
        : "=r"(r0), "=r"(r1), "=r"(r2), "=r"(r3) : "r"(a));
}
__device__ __forceinline__ void ldsm_x4t(uint32_t& r0, uint32_t& r1, uint32_t& r2, uint32_t& r3, uint32_t a) {
    asm volatile("ldmatrix.sync.aligned.m8n8.x4.trans.shared.b16 {%0,%1,%2,%3}, [%4];"
        : "=r"(r0), "=r"(r1), "=r"(r2), "=r"(r3) : "r"(a));
}
__device__ __forceinline__ void mma_bf16(float* d, uint32_t a0, uint32_t a1, uint32_t a2, uint32_t a3,
                                         uint32_t b0, uint32_t b1) {
    asm volatile("mma.sync.aligned.m16n8k16.row.col.f32.bf16.bf16.f32 "
        "{%0,%1,%2,%3}, {%4,%5,%6,%7}, {%8,%9}, {%0,%1,%2,%3};"
        : "+f"(d[0]), "+f"(d[1]), "+f"(d[2]), "+f"(d[3])
        : "r"(a0), "r"(a1), "r"(a2), "r"(a3), "r"(b0), "r"(b1));
}
__device__ __forceinline__ void cp16(uint32_t sdst, const void* gsrc) {
    asm volatile("cp.async.cg.shared.global [%0], [%1], 16;" :: "r"(sdst), "l"(gsrc));
}
#define CP_COMMIT() asm volatile("cp.async.commit_group;")
template<int N> __device__ __forceinline__ void cp_wait() {
    asm volatile("cp.async.wait_group %0;" :: "n"(N));
}
__device__ __forceinline__ void copy_async(uint32_t sdst, const unsigned char* gsrc, uint32_t bytes, int tid) {
    for (uint32_t i = (uint32_t)tid * 16u; i < bytes; i += (uint32_t)TPB * 16u)
        cp16(sdst + i, gsrc + i);
}
__device__ __host__ __forceinline__ uint32_t swz_off(uint32_t row, uint32_t cb, uint32_t rowB) {
    return row * rowB + (cb & ~127u) + ((cb & 127u) ^ ((row & 7u) << 4));
}

// ---------------- weight converter (unchanged layouts) ----------------
__global__ void convert_weights_kernel(const float* __restrict__ W0, const float* __restrict__ b0,
                                       const float* __restrict__ Wh, const float* __restrict__ bh,
                                       const float* __restrict__ Wout)
{
    int idx = blockIdx.x * blockDim.x + threadIdx.x;
    if (idx >= 139264) return;
    float w; uint32_t img, part, rowB, k, n;
    if (idx < 8192) {                       // L0: K=64 (row 63 = bias), N=128
        k = (uint32_t)(idx >> 7); n = (uint32_t)(idx & 127);
        img = IMG_L0; part = P_L0; rowB = 256;
        w = (k < 63) ? W0[k * 128 + n] : b0[n];
    } else if (idx < 131072) {              // hidden: K=192 (row 191 = bias), N=128
        int t = idx - 8192; int l = t / 24576; int r = t % 24576;
        k = (uint32_t)(r >> 7); n = (uint32_t)(r & 127);
        img = IMG_HID(l + 1); part = P_HID; rowB = 256;
        w = (k < 191) ? Wh[((uint32_t)l * 191 + k) * 128 + n] : bh[l * 128 + n];
    } else {                                // out: K=128, N=48 padded to 64
        int t = idx - 131072;
        k = (uint32_t)(t >> 6); n = (uint32_t)(t & 63);
        img = IMG_OUT; part = P_OUT; rowB = 128;
        w = (n < 48) ? Wout[k * 48 + n] : 0.0f;
    }
    __nv_bfloat16 hi = __float2bfloat16(w);
    __nv_bfloat16 lo = __float2bfloat16(w - __bfloat162float(hi));
    uint32_t off = swz_off(k, n * 2, rowB);
    *(__nv_bfloat16*)(g_wscratch + img + off)        = hi;
    *(__nv_bfloat16*)(g_wscratch + img + part + off) = lo;
}

// ---------------- small math utils ----------------
__device__ __forceinline__ float3 norm3(float3 v, float eps) {
    float n = sqrtf(v.x * v.x + v.y * v.y + v.z * v.z);
    float inv = 1.0f / fmaxf(n, eps);
    return make_float3(v.x * inv, v.y * inv, v.z * inv);
}
__device__ __forceinline__ float3 cross3(float3 a, float3 b) {
    return make_float3(a.y * b.z - a.z * b.y, a.z * b.x - a.x * b.z, a.x * b.y - a.y * b.x);
}
__device__ __forceinline__ uint32_t packbf(float a, float b) {
    __nv_bfloat162 p; p.x = __float2bfloat16(a); p.y = __float2bfloat16(b);
    return *(uint32_t*)&p;
}

// one k-step MMA against HALVES*64 output cols of the weight region
template<int HALVES, int ROWB>
__device__ __forceinline__ void bpass(uint32_t sbw, int s, int lane,
                                      const uint32_t* a, float (*acc)[4])
{
    const uint32_t l15 = (uint32_t)(lane & 15);
    const uint32_t lh4 = (uint32_t)(lane >> 4) << 4;
    const uint32_t krow = (uint32_t)(16 * s) + l15;
    #pragma unroll
    for (int half = 0; half < HALVES; half++) {
        uint32_t b[8][2];
        #pragma unroll
        for (int t = 0; t < 4; t++) {
            uint32_t cb = (uint32_t)(half * 128 + t * 32) + lh4;
            ldsm_x4t(b[2 * t][0], b[2 * t][1], b[2 * t + 1][0], b[2 * t + 1][1],
                     sbw + swz_off(krow, cb, (uint32_t)ROWB));
        }
        #pragma unroll
        for (int t = 0; t < 8; t++)
            mma_bf16(acc[half * 8 + t], a[0], a[1], a[2], a[3], b[t][0], b[t][1]);
    }
}
// load one enc k-step A-fragment (rows m0..m0+16, enc cols 16*se..)
__device__ __forceinline__ void lda_enc(uint32_t sbe, int se, int m0, int lane, uint32_t* a) {
    const uint32_t l15 = (uint32_t)(lane & 15);
    const uint32_t lh4 = (uint32_t)(lane >> 4) << 4;
    ldsm_x4(a[0], a[1], a[2], a[3],
            sbe + swz_off((uint32_t)m0 + l15, (uint32_t)(se * 32) + lh4, 128u));
}

// ---------------- main kernel ----------------
extern "C" __global__ void __launch_bounds__(TPB, 1)
fourier_mma_kernel(const float* __restrict__ x, const float* __restrict__ view,
                   const float* __restrict__ normal, const float* __restrict__ light,
                   const float* __restrict__ bout, float* __restrict__ out)
{
    extern __shared__ __align__(16) unsigned char smem[];
    const uint32_t sb = smem_u32(smem);
    const int tid  = threadIdx.x;
    const int lane = tid & 31;
    const int warp = tid >> 5;
    const int m0   = warp * 16;          // warp owns points m0..m0+15

    // prefetch L0 weights (groups 1, 2)
    copy_async(sb + SM_WHI, g_wscratch + IMG_L0, P_L0, tid);        CP_COMMIT();
    copy_async(sb + SM_WLO, g_wscratch + IMG_L0 + P_L0, P_L0, tid); CP_COMMIT();

    // ---- geometry + Chebyshev + Fourier encoding (threads 0..127, thread = point) ----
    if (tid < PTS) {
        const int pt = blockIdx.x * PTS + tid;
        float3 xx = make_float3(x[pt * 3 + 0], x[pt * 3 + 1], x[pt * 3 + 2]);
        float3 vv = make_float3(view[pt * 3 + 0], view[pt * 3 + 1], view[pt * 3 + 2]);
        float3 nn = make_float3(normal[pt * 3 + 0], normal[pt * 3 + 1], normal[pt * 3 + 2]);
        float3 ll = make_float3(light[pt * 3 + 0], light[pt * 3 + 1], light[pt * 3 + 2]);

        float3 n = norm3(nn, 1e-6f);
        float sgn = (n.z >= 0.0f) ? 1.0f : -1.0f;
        float s_z = sgn + n.z;
        float safe = (fabsf(s_z) < 1e-6f) ? copysignf(1e-6f, s_z) : s_z;
        float a = -1.0f / safe;
        float b = n.x * n.y * a;
        float3 s = make_float3(n.x * n.x * a * sgn + 1.0f, b * sgn, -n.x * sgn);
        s = norm3(s, 1e-6f);
        float3 t = norm3(cross3(s, n), 1e-6f);
        s = norm3(cross3(n, t), 1e-6f);

        float3 v = norm3(vv, 1e-6f);
        float3 wo = norm3(make_float3(v.x * s.x + v.y * s.y + v.z * s.z,
                                      v.x * t.x + v.y * t.y + v.z * t.z,
                                      v.x * n.x + v.y * n.y + v.z * n.z), 1e-7f);
        float3 wi = norm3(make_float3(ll.x * s.x + ll.y * s.y + ll.z * s.z,
                                      ll.x * t.x + ll.y * t.y + ll.z * t.z,
                                      ll.x * n.x + ll.y * n.y + ll.z * n.z), 1e-7f);
        float num = -(wi.x * wo.x + wi.y * wo.y);
        float den = sqrtf((wo.x * wo.x + wo.y * wo.y) * (wi.x * wi.x + wi.y * wi.y));
        float cp = fminf(1.0f, fmaxf(-1.0f, num / den));

        float c0 = 1.0f, c1 = cp;
        *(float*)(smem + SM_CHEB + tid * 68 + 0) = c0;
        *(float*)(smem + SM_CHEB + tid * 68 + 4) = c1;
        #pragma unroll
        for (int o = 2; o < 16; o++) {
            float c2v = 2.0f * cp * c1 - c0;
            *(float*)(smem + SM_CHEB + tid * 68 + o * 4) = c2v;
            c0 = c1; c1 = c2v;
        }

        float enc[64];
        enc[0] = xx.x; enc[1] = xx.y; enc[2] = xx.z;
        float fr = 1.0f;
        #pragma unroll
        for (int f = 0; f < 10; f++) {
            float sv, cv;
            sincosf(xx.x * fr, &sv, &cv); enc[3 + f * 3 + 0] = sv; enc[33 + f * 3 + 0] = cv;
            sincosf(xx.y * fr, &sv, &cv); enc[3 + f * 3 + 1] = sv; enc[33 + f * 3 + 1] = cv;
            sincosf(xx.z * fr, &sv, &cv); enc[3 + f * 3 + 2] = sv; enc[33 + f * 3 + 2] = cv;
            fr *= 2.0f;
        }
        enc[63] = 1.0f;                      // bias slot

        #pragma unroll
        for (int j = 0; j < 32; j++) {
            float e0 = enc[2 * j], e1 = enc[2 * j + 1];
            __nv_bfloat16 h0 = __float2bfloat16(e0), h1 = __float2bfloat16(e1);
            float l0 = e0 - __bfloat162float(h0), l1 = e1 - __bfloat162float(h1);
            __nv_bfloat162 hp; hp.x = h0; hp.y = h1;
            uint32_t off = swz_off((uint32_t)tid, 4u * (uint32_t)j, 128u);
            *(uint32_t*)(smem + SM_ENCH + off) = *(uint32_t*)&hp;
            *(uint32_t*)(smem + SM_ENCL + off) = packbf(l0, l1);
        }
    }
    cp_wait<1>();        // W_hi(L0) done
    __syncthreads();

    uint32_t ahi[32], alo[32];   // activation A-fragments (k = 0..127), hi/lo

    // ================= layer 0 (K=64, enc-only A) =================
    {
        float acc[16][4] = {};
        #pragma unroll
        for (int se = 0; se < 4; se++) {
            uint32_t a[4]; lda_enc(sb + SM_ENCH, se, m0, lane, a);
            bpass<2, 256>(sb + SM_WHI, se, lane, a, acc);
        }
        #pragma unroll
        for (int se = 0; se < 4; se++) {
            uint32_t a[4]; lda_enc(sb + SM_ENCL, se, m0, lane, a);
            bpass<2, 256>(sb + SM_WHI, se, lane, a, acc);
        }
        __syncthreads();
        copy_async(sb + SM_WHI, g_wscratch + IMG_HID(1), P_HID, tid); CP_COMMIT();
        cp_wait<1>();        // W_lo(L0) done
        __syncthreads();
        #pragma unroll
        for (int se = 0; se < 4; se++) {
            uint32_t a[4]; lda_enc(sb + SM_ENCH, se, m0, lane, a);
            bpass<2, 256>(sb + SM_WLO, se, lane, a, acc);
        }
        __syncthreads();
        copy_async(sb + SM_WLO, g_wscratch + IMG_HID(1) + P_HID, P_HID, tid); CP_COMMIT();
        // epilogue: C-fragments -> next-layer A-fragments (leaky-relu + hi/lo split)
        #pragma unroll
        for (int t = 0; t < 8; t++) {
            #pragma unroll
            for (int u = 0; u < 2; u++) {          // u=0: rows r / a0,a2 ; u=1: rows r+8 / a1,a3
                float v0 = acc[2 * t][2 * u + 0], v1 = acc[2 * t][2 * u + 1];
                float w0 = acc[2 * t + 1][2 * u + 0], w1 = acc[2 * t + 1][2 * u + 1];
                v0 = v0 > 0.0f ? v0 : 0.01f * v0;  v1 = v1 > 0.0f ? v1 : 0.01f * v1;
                w0 = w0 > 0.0f ? w0 : 0.01f * w0;  w1 = w1 > 0.0f ? w1 : 0.01f * w1;
                __nv_bfloat16 hv0 = __float2bfloat16(v0), hv1 = __float2bfloat16(v1);
                __nv_bfloat16 hw0 = __float2bfloat16(w0), hw1 = __float2bfloat16(w1);
                __nv_bfloat162 pv; pv.x = hv0; pv.y = hv1;
                __nv_bfloat162 pw; pw.x = hw0; pw.y = hw1;
                ahi[4 * t + u]     = *(uint32_t*)&pv;
                ahi[4 * t + 2 + u] = *(uint32_t*)&pw;
                alo[4 * t + u]     = packbf(v0 - __bfloat162float(hv0), v1 - __bfloat162float(hv1));
                alo[4 * t + 2 + u] = packbf(w0 - __bfloat162float(hw0), w1 - __bfloat162float(hw1));
            }
        }
    }

    // ================= hidden layers 1..5 (K=192 = 128 reg + 64 enc) =================
    #pragma unroll 1
    for (int l = 1; l <= 5; l++) {
        const unsigned char* nimg = g_wscratch + ((l == 5) ? IMG_OUT : IMG_HID(l + 1));
        const uint32_t npart = (l == 5) ? P_OUT : P_HID;
        cp_wait<1>();        // W_hi(l) done
        __syncthreads();
        float acc[16][4] = {};
        #pragma unroll
        for (int s = 0; s < 8; s++) bpass<2, 256>(sb + SM_WHI, s, lane, &ahi[4 * s], acc);
        #pragma unroll
        for (int se = 0; se < 4; se++) {
            uint32_t a[4]; lda_enc(sb + SM_ENCH, se, m0, lane, a);
            bpass<2, 256>(sb + SM_WHI, 8 + se, lane, a, acc);
        }
        #pragma unroll
        for (int s = 0; s < 8; s++) bpass<2, 256>(sb + SM_WHI, s, lane, &alo[4 * s], acc);
        #pragma unroll
        for (int se = 0; se < 4; se++) {
            uint32_t a[4]; lda_enc(sb + SM_ENCL, se, m0, lane, a);
            bpass<2, 256>(sb + SM_WHI, 8 + se, lane, a, acc);
        }
        __syncthreads();
        copy_async(sb + SM_WHI, nimg, npart, tid); CP_COMMIT();
        cp_wait<1>();        // W_lo(l) done
        __syncthreads();
        #pragma unroll
        for (int s = 0; s < 8; s++) bpass<2, 256>(sb + SM_WLO, s, lane, &ahi[4 * s], acc);
        #pragma unroll
        for (int se = 0; se < 4; se++) {
            uint32_t a[4]; lda_enc(sb + SM_ENCH, se, m0, lane, a);
            bpass<2, 256>(sb + SM_WLO, 8 + se, lane, a, acc);
        }
        __syncthreads();
        copy_async(sb + SM_WLO, nimg + npart, npart, tid); CP_COMMIT();
        // epilogue (register-only)
        #pragma unroll
        for (int t = 0; t < 8; t++) {
            #pragma unroll
            for (int u = 0; u < 2; u++) {
                float v0 = acc[2 * t][2 * u + 0], v1 = acc[2 * t][2 * u + 1];
                float w0 = acc[2 * t + 1][2 * u + 0], w1 = acc[2 * t + 1][2 * u + 1];
                v0 = v0 > 0.0f ? v0 : 0.01f * v0;  v1 = v1 > 0.0f ? v1 : 0.01f * v1;
                w0 = w0 > 0.0f ? w0 : 0.01f * w0;  w1 = w1 > 0.0f ? w1 : 0.01f * w1;
                __nv_bfloat16 hv0 = __float2bfloat16(v0), hv1 = __float2bfloat16(v1);
                __nv_bfloat16 hw0 = __float2bfloat16(w0), hw1 = __float2bfloat16(w1);
                __nv_bfloat162 pv; pv.x = hv0; pv.y = hv1;
                __nv_bfloat162 pw; pw.x = hw0; pw.y = hw1;
                ahi[4 * t + u]     = *(uint32_t*)&pv;
                ahi[4 * t + 2 + u] = *(uint32_t*)&pw;
                alo[4 * t + u]     = packbf(v0 - __bfloat162float(hv0), v1 - __bfloat162float(hv1));
                alo[4 * t + 2 + u] = packbf(w0 - __bfloat162float(hw0), w1 - __bfloat162float(hw1));
            }
        }
    }

    // ================= output layer (K=128 all-register A, N=64 padded) =================
    {
        cp_wait<1>();        // W_hi(out) done
        __syncthreads();
        float acc[8][4] = {};
        #pragma unroll
        for (int s = 0; s < 8; s++) bpass<1, 128>(sb + SM_WHI, s, lane, &ahi[4 * s], acc);
        #pragma unroll
        for (int s = 0; s < 8; s++) bpass<1, 128>(sb + SM_WHI, s, lane, &alo[4 * s], acc);
        cp_wait<0>();        // W_lo(out) done
        __syncthreads();
        #pragma unroll
        for (int s = 0; s < 8; s++) bpass<1, 128>(sb + SM_WLO, s, lane, &ahi[4 * s], acc);
        __syncthreads();     // everyone done reading SM_WHI -> reuse as staging

        // stage coeffs into SM_WHI region: [pt][65 f32]
        const int r  = lane >> 2;
        const int c2 = (lane & 3) * 2;
        #pragma unroll
        for (int t = 0; t < 8; t++) {
            float* dst0 = (float*)(smem + SM_WHI) + (m0 + r) * 65 + 8 * t + c2;
            float* dst1 = (float*)(smem + SM_WHI) + (m0 + r + 8) * 65 + 8 * t + c2;
            dst0[0] = acc[t][0]; dst0[1] = acc[t][1];
            dst1[0] = acc[t][2]; dst1[1] = acc[t][3];
        }
        __syncthreads();

        // contraction with Chebyshev basis (threads 0..127, thread = point)
        if (tid < PTS) {
            float ch[16];
            #pragma unroll
            for (int o = 0; o < 16; o++) ch[o] = *(float*)(smem + SM_CHEB + tid * 68 + o * 4);
            const float* cf = (float*)(smem + SM_WHI) + tid * 65;
            const int pt = blockIdx.x * PTS + tid;
            #pragma unroll
            for (int f = 0; f < 3; f++) {
                float sum = 0.0f;
                #pragma unroll
                for (int o = 0; o < 16; o++)
                    sum += (cf[f * 16 + o] + __ldg(bout + f * 16 + o)) * ch[o];
                out[pt * 3 + f] = sum;
            }
        }
    }
}

// ---------------- launch ----------------
extern "C" void kernel_launch(void* const* d_in, const int* in_sizes, int n_in,
                              void* d_out, int out_size)
{
    const float* x      = (const float*)d_in[0];
    const float* view   = (const float*)d_in[1];
    const float* normal = (const float*)d_in[2];
    const float* light  = (const float*)d_in[3];
    const float* W0     = (const float*)d_in[4];
    const float* b0     = (const float*)d_in[5];
    const float* Wh     = (const float*)d_in[6];
    const float* bh     = (const float*)d_in[7];
    const float* Wout   = (const float*)d_in[8];
    const float* bout   = (const float*)d_in[9];
    float* out = (float*)d_out;

    convert_weights_kernel<<<544, 256>>>(W0, b0, Wh, bh, Wout);

    cudaFuncSetAttribute(fourier_mma_kernel,
                         cudaFuncAttributeMaxDynamicSharedMemorySize, (int)SM_TOTAL);
    fourier_mma_kernel<<<NBLK, TPB, SM_TOTAL>>>(x, view, normal, light, bout, out);
}

// round 8
// speedup vs baseline: 1.1362x; 1.1362x over previous
#include <cuda_runtime.h>
#include <cuda_bf16.h>
#include <math.h>
#include <stdint.h>

#define TPB   256
#define PTS   128
#define NBLK  2048

// ---------------- smem layout (bytes) ----------------
#define SM_AHI  0u            // A hi: 128 pts x 384B (192 bf16: h[0..127], enc[128..190], bias[191])
#define SM_ALO  49152u        // A lo
#define SM_WHI  98304u        // weight hi buffer (<=49152)
#define SM_WLO  147456u       // weight lo buffer
#define SM_CHEB 196608u       // 128 x 68B
#define SM_MBAR 205312u       // 2 mbarriers (16B)
#define SM_TOTAL 205344u

// ---------------- global weight scratch (pre-swizzled smem images) ----------------
#define IMG_L0  0u
#define P_L0    16384u        // 64 rows x 256B
#define P_HID   49152u        // 192 rows x 256B
#define IMG_HID(l) (32768u + (uint32_t)((l) - 1) * 98304u)   // l = 1..5
#define IMG_OUT 524288u
#define P_OUT   16384u        // 128 rows x 128B (N padded to 64)
__device__ __align__(16) unsigned char g_wscratch[557056];

// ---------------- PTX helpers ----------------
__device__ __forceinline__ uint32_t smem_u32(const void* p) {
    uint32_t a;
    asm("{ .reg .u64 t; cvta.to.shared.u64 t, %1; cvt.u32.u64 %0, t; }" : "=r"(a) : "l"(p));
    return a;
}
__device__ __forceinline__ void ldsm_x4(uint32_t& r0, uint32_t& r1, uint32_t& r2, uint32_t& r3, uint32_t a) {
    asm volatile("ldmatrix.sync.aligned.m8n8.x4.shared.b16 {%0,%1,%2,%3}, [%4];"
        : "=r"(r0), "=r"(r1), "=r"(r2), "=r"(r3) : "r"(a));
}
__device__ __forceinline__ void ldsm_x4t(uint32_t& r0, uint32_t& r1, uint32_t& r2, uint32_t& r3, uint32_t a) {
    asm volatile("ldmatrix.sync.aligned.m8n8.x4.trans.shared.b16 {%0,%1,%2,%3}, [%4];"
        : "=r"(r0), "=r"(r1), "=r"(r2), "=r"(r3) : "r"(a));
}
__device__ __forceinline__ void mma_bf16(float* d, uint32_t a0, uint32_t a1, uint32_t a2, uint32_t a3,
                                         uint32_t b0, uint32_t b1) {
    asm volatile("mma.sync.aligned.m16n8k16.row.col.f32.bf16.bf16.f32 "
        "{%0,%1,%2,%3}, {%4,%5,%6,%7}, {%8,%9}, {%0,%1,%2,%3};"
        : "+f"(d[0]), "+f"(d[1]), "+f"(d[2]), "+f"(d[3])
        : "r"(a0), "r"(a1), "r"(a2), "r"(a3), "r"(b0), "r"(b1));
}
#define MBARRIER_INIT(mb, c) asm volatile("mbarrier.init.shared.b64 [%0], %1;" :: "r"((uint32_t)(mb)), "r"((uint32_t)(c)) : "memory")
#define MBAR_WAIT(mb, par) do {                                                     \
    uint32_t _mb = (uint32_t)(mb), _p = (uint32_t)(par);                            \
    asm volatile("{\n\t.reg .pred P1;\n\tWL_%=:\n\t"                                \
        "mbarrier.try_wait.parity.acquire.cta.shared::cta.b64 P1, [%0], %1, 0x989680;\n\t" \
        "@P1 bra.uni WD_%=;\n\tbra.uni WL_%=;\n\tWD_%=:\n\t}"                       \
        :: "r"(_mb), "r"(_p) : "memory");                                           \
} while (0)
// one-thread weight fetch: expect_tx + bulk async copy (zero warp issue cost)
__device__ __forceinline__ void w_fetch(uint32_t mb, uint32_t sdst, const unsigned char* gsrc, uint32_t bytes) {
    asm volatile("mbarrier.arrive.expect_tx.shared.b64 _, [%0], %1;"
        :: "r"(mb), "r"(bytes) : "memory");
    asm volatile("cp.async.bulk.shared::cluster.global.mbarrier::complete_tx::bytes [%0], [%1], %2, [%3];"
        :: "r"(sdst), "l"(gsrc), "r"(bytes), "r"(mb) : "memory");
}
__device__ __host__ __forceinline__ uint32_t swz_off(uint32_t row, uint32_t cb, uint32_t rowB) {
    return row * rowB + (cb & ~127u) + ((cb & 127u) ^ ((row & 7u) << 4));
}

// ---------------- weight converter ----------------
__global__ void convert_weights_kernel(const float* __restrict__ W0, const float* __restrict__ b0,
                                       const float* __restrict__ Wh, const float* __restrict__ bh,
                                       const float* __restrict__ Wout)
{
    int idx = blockIdx.x * blockDim.x + threadIdx.x;
    if (idx >= 139264) return;
    float w; uint32_t img, part, rowB, k, n;
    if (idx < 8192) {                       // L0: K=64 (row 63 = bias), N=128
        k = (uint32_t)(idx >> 7); n = (uint32_t)(idx & 127);
        img = IMG_L0; part = P_L0; rowB = 256;
        w = (k < 63) ? W0[k * 128 + n] : b0[n];
    } else if (idx < 131072) {              // hidden: K=192 (row 191 = bias), N=128
        int t = idx - 8192; int l = t / 24576; int r = t % 24576;
        k = (uint32_t)(r >> 7); n = (uint32_t)(r & 127);
        img = IMG_HID(l + 1); part = P_HID; rowB = 256;
        w = (k < 191) ? Wh[((uint32_t)l * 191 + k) * 128 + n] : bh[l * 128 + n];
    } else {                                // out: K=128, N=48 padded to 64
        int t = idx - 131072;
        k = (uint32_t)(t >> 6); n = (uint32_t)(t & 63);
        img = IMG_OUT; part = P_OUT; rowB = 128;
        w = (n < 48) ? Wout[k * 48 + n] : 0.0f;
    }
    __nv_bfloat16 hi = __float2bfloat16(w);
    __nv_bfloat16 lo = __float2bfloat16(w - __bfloat162float(hi));
    uint32_t off = swz_off(k, n * 2, rowB);
    *(__nv_bfloat16*)(g_wscratch + img + off)        = hi;
    *(__nv_bfloat16*)(g_wscratch + img + part + off) = lo;
}

// ---------------- small math utils ----------------
__device__ __forceinline__ float3 norm3(float3 v, float eps) {
    float n = sqrtf(v.x * v.x + v.y * v.y + v.z * v.z);
    float inv = 1.0f / fmaxf(n, eps);
    return make_float3(v.x * inv, v.y * inv, v.z * inv);
}
__device__ __forceinline__ float3 cross3(float3 a, float3 b) {
    return make_float3(a.y * b.z - a.z * b.y, a.z * b.x - a.x * b.z, a.x * b.y - a.y * b.x);
}
__device__ __forceinline__ uint32_t packbf(float a, float b) {
    __nv_bfloat162 p; p.x = __float2bfloat16(a); p.y = __float2bfloat16(b);
    return *(uint32_t*)&p;
}

// ---------------- MMA pass over one weight region ----------------
// Warp computes rows [m0, m0+16*MT) x cols [n0, n0+8*NT) of the layer output.
template<int KSTEPS, int MT, int NT, int ROWB, bool DUAL>
__device__ __forceinline__ void mma_pass(uint32_t sb, uint32_t wreg, int kbaseA,
                                         int m0, int n0, int lane, float (&acc)[MT][NT][4])
{
    const uint32_t l15 = (uint32_t)(lane & 15);
    const uint32_t lh  = (uint32_t)(lane >> 4);
    #pragma unroll
    for (int s = 0; s < KSTEPS; s++) {
        uint32_t b[NT][2];
        #pragma unroll
        for (int t = 0; t < NT / 2; t++) {
            uint32_t krow = (uint32_t)(16 * s) + l15;
            uint32_t cb = (uint32_t)(n0 * 2 + t * 32) + (lh << 4);
            uint32_t off = swz_off(krow, cb, (uint32_t)ROWB);
            ldsm_x4t(b[2 * t][0], b[2 * t][1], b[2 * t + 1][0], b[2 * t + 1][1], sb + wreg + off);
        }
        const uint32_t cbA = (uint32_t)((kbaseA + 16 * s) * 2) + (lh << 4);
        #pragma unroll
        for (int m = 0; m < MT; m++) {
            uint32_t row = (uint32_t)(m0 + 16 * m) + l15;
            uint32_t off = swz_off(row, cbA, 384u);
            uint32_t a0, a1, a2, a3;
            ldsm_x4(a0, a1, a2, a3, sb + SM_AHI + off);
            #pragma unroll
            for (int n = 0; n < NT; n++) mma_bf16(acc[m][n], a0, a1, a2, a3, b[n][0], b[n][1]);
            if (DUAL) {
                ldsm_x4(a0, a1, a2, a3, sb + SM_ALO + off);
                #pragma unroll
                for (int n = 0; n < NT; n++) mma_bf16(acc[m][n], a0, a1, a2, a3, b[n][0], b[n][1]);
            }
        }
    }
}

// hidden-layer epilogue: leaky-relu, split hi/lo, store into A h-region
__device__ __forceinline__ void epilogue_store(unsigned char* smem, float (&acc)[2][8][4],
                                               int lane, int m0, int n0)
{
    const int r  = lane >> 2;
    const int c2 = (lane & 3) * 2;
    #pragma unroll
    for (int m = 0; m < 2; m++)
        #pragma unroll
        for (int n = 0; n < 8; n++) {
            const uint32_t cb = (uint32_t)((n0 + 8 * n + c2) * 2);
            #pragma unroll
            for (int h = 0; h < 2; h++) {
                uint32_t row = (uint32_t)(m0 + 16 * m + r + 8 * h);
                float v0 = acc[m][n][2 * h + 0];
                float v1 = acc[m][n][2 * h + 1];
                v0 = v0 > 0.0f ? v0 : 0.01f * v0;
                v1 = v1 > 0.0f ? v1 : 0.01f * v1;
                __nv_bfloat16 h0 = __float2bfloat16(v0), h1 = __float2bfloat16(v1);
                float l0 = v0 - __bfloat162float(h0), l1 = v1 - __bfloat162float(h1);
                __nv_bfloat162 hp; hp.x = h0; hp.y = h1;
                uint32_t off = swz_off(row, cb, 384u);
                *(uint32_t*)(smem + SM_AHI + off) = *(uint32_t*)&hp;
                *(uint32_t*)(smem + SM_ALO + off) = packbf(l0, l1);
            }
        }
}

// ---------------- main kernel ----------------
extern "C" __global__ void __launch_bounds__(TPB, 1)
fourier_mma_kernel(const float* __restrict__ x, const float* __restrict__ view,
                   const float* __restrict__ normal, const float* __restrict__ light,
                   const float* __restrict__ bout, float* __restrict__ out)
{
    extern __shared__ __align__(16) unsigned char smem[];
    const uint32_t sb = smem_u32(smem);
    const uint32_t mb0 = sb + SM_MBAR;
    const uint32_t mb1 = sb + SM_MBAR + 8;
    const int tid  = threadIdx.x;
    const int lane = tid & 31;
    const int warp = tid >> 5;

    // init mbarriers + kick off L0 weight fetches (single thread, async engine)
    if (tid == 0) {
        MBARRIER_INIT(mb0, 1);
        MBARRIER_INIT(mb1, 1);
        w_fetch(mb0, sb + SM_WHI, g_wscratch + IMG_L0, P_L0);
        w_fetch(mb1, sb + SM_WLO, g_wscratch + IMG_L0 + P_L0, P_L0);
    }

    // ---- geometry + Chebyshev + Fourier encoding (threads 0..127, thread = point) ----
    if (tid < PTS) {
        const int pt = blockIdx.x * PTS + tid;
        float3 xx = make_float3(x[pt * 3 + 0], x[pt * 3 + 1], x[pt * 3 + 2]);
        float3 vv = make_float3(view[pt * 3 + 0], view[pt * 3 + 1], view[pt * 3 + 2]);
        float3 nn = make_float3(normal[pt * 3 + 0], normal[pt * 3 + 1], normal[pt * 3 + 2]);
        float3 ll = make_float3(light[pt * 3 + 0], light[pt * 3 + 1], light[pt * 3 + 2]);

        float3 n = norm3(nn, 1e-6f);
        float sgn = (n.z >= 0.0f) ? 1.0f : -1.0f;
        float s_z = sgn + n.z;
        float safe = (fabsf(s_z) < 1e-6f) ? copysignf(1e-6f, s_z) : s_z;
        float a = -1.0f / safe;
        float b = n.x * n.y * a;
        float3 s = make_float3(n.x * n.x * a * sgn + 1.0f, b * sgn, -n.x * sgn);
        s = norm3(s, 1e-6f);
        float3 t = norm3(cross3(s, n), 1e-6f);
        s = norm3(cross3(n, t), 1e-6f);

        float3 v = norm3(vv, 1e-6f);
        float3 wo = norm3(make_float3(v.x * s.x + v.y * s.y + v.z * s.z,
                                      v.x * t.x + v.y * t.y + v.z * t.z,
                                      v.x * n.x + v.y * n.y + v.z * n.z), 1e-7f);
        float3 wi = norm3(make_float3(ll.x * s.x + ll.y * s.y + ll.z * s.z,
                                      ll.x * t.x + ll.y * t.y + ll.z * t.z,
                                      ll.x * n.x + ll.y * n.y + ll.z * n.z), 1e-7f);
        float num = -(wi.x * wo.x + wi.y * wo.y);
        float den = sqrtf((wo.x * wo.x + wo.y * wo.y) * (wi.x * wi.x + wi.y * wi.y));
        float cp = fminf(1.0f, fmaxf(-1.0f, num / den));

        float c0 = 1.0f, c1 = cp;
        *(float*)(smem + SM_CHEB + tid * 68 + 0) = c0;
        *(float*)(smem + SM_CHEB + tid * 68 + 4) = c1;
        #pragma unroll
        for (int o = 2; o < 16; o++) {
            float c2v = 2.0f * cp * c1 - c0;
            *(float*)(smem + SM_CHEB + tid * 68 + o * 4) = c2v;
            c0 = c1; c1 = c2v;
        }

        float enc[64];
        enc[0] = xx.x; enc[1] = xx.y; enc[2] = xx.z;
        float fr = 1.0f;
        #pragma unroll
        for (int f = 0; f < 10; f++) {
            float sv, cv;
            sincosf(xx.x * fr, &sv, &cv); enc[3 + f * 3 + 0] = sv; enc[33 + f * 3 + 0] = cv;
            sincosf(xx.y * fr, &sv, &cv); enc[3 + f * 3 + 1] = sv; enc[33 + f * 3 + 1] = cv;
            sincosf(xx.z * fr, &sv, &cv); enc[3 + f * 3 + 2] = sv; enc[33 + f * 3 + 2] = cv;
            fr *= 2.0f;
        }
        enc[63] = 1.0f;                      // bias slot

        #pragma unroll
        for (int j = 0; j < 32; j++) {
            float e0 = enc[2 * j], e1 = enc[2 * j + 1];
            __nv_bfloat16 h0 = __float2bfloat16(e0), h1 = __float2bfloat16(e1);
            float l0 = e0 - __bfloat162float(h0), l1 = e1 - __bfloat162float(h1);
            __nv_bfloat162 hp; hp.x = h0; hp.y = h1;
            uint32_t off = swz_off((uint32_t)tid, 256u + 4u * (uint32_t)j, 384u);
            *(uint32_t*)(smem + SM_AHI + off) = *(uint32_t*)&hp;
            *(uint32_t*)(smem + SM_ALO + off) = packbf(l0, l1);
        }
    }
    __syncthreads();          // A/cheb visible; mbarrier init visible to all waiters
    int ph0 = 0, ph1 = 0;

    // warp tiling: 4 m-groups x 2 n-groups
    const int mg = warp >> 1;        // 0..3
    const int ng = warp & 1;         // 0..1
    const int m0 = mg * 32;
    const int n0h = ng * 64;         // hidden layers: 64 cols per warp

    // ================= layer 0 (K=64, A cols 128..191) =================
    {
        MBAR_WAIT(mb0, ph0); ph0 ^= 1;      // W_hi(L0) landed
        float acc[2][8][4] = {};
        mma_pass<4, 2, 8, 256, true>(sb, SM_WHI, 128, m0, n0h, lane, acc);
        __syncthreads();                    // all warps done reading W_HI
        if (tid == 0) w_fetch(mb0, sb + SM_WHI, g_wscratch + IMG_HID(1), P_HID);
        MBAR_WAIT(mb1, ph1); ph1 ^= 1;      // W_lo(L0) landed
        mma_pass<4, 2, 8, 256, false>(sb, SM_WLO, 128, m0, n0h, lane, acc);
        __syncthreads();                    // all warps done reading W_LO
        if (tid == 0) w_fetch(mb1, sb + SM_WLO, g_wscratch + IMG_HID(1) + P_HID, P_HID);
        epilogue_store(smem, acc, lane, m0, n0h);
        __syncthreads();                    // A(l+1) visible
    }

    // ================= hidden layers 1..5 (K=192) =================
    #pragma unroll 1
    for (int l = 1; l <= 5; l++) {
        const unsigned char* nimg = g_wscratch + ((l == 5) ? IMG_OUT : IMG_HID(l + 1));
        const uint32_t npart = (l == 5) ? P_OUT : P_HID;
        MBAR_WAIT(mb0, ph0); ph0 ^= 1;
        float acc[2][8][4] = {};
        mma_pass<12, 2, 8, 256, true>(sb, SM_WHI, 0, m0, n0h, lane, acc);
        __syncthreads();
        if (tid == 0) w_fetch(mb0, sb + SM_WHI, nimg, npart);
        MBAR_WAIT(mb1, ph1); ph1 ^= 1;
        mma_pass<12, 2, 8, 256, false>(sb, SM_WLO, 0, m0, n0h, lane, acc);
        __syncthreads();
        if (tid == 0) w_fetch(mb1, sb + SM_WLO, nimg + npart, npart);
        epilogue_store(smem, acc, lane, m0, n0h);
        __syncthreads();
    }

    // ================= output layer (K=128, N=64 padded) =================
    {
        const int n0o = ng * 32;     // 32 cols per warp
        MBAR_WAIT(mb0, ph0); ph0 ^= 1;
        float acc[2][4][4] = {};
        mma_pass<8, 2, 4, 128, true>(sb, SM_WHI, 0, m0, n0o, lane, acc);
        MBAR_WAIT(mb1, ph1); ph1 ^= 1;
        mma_pass<8, 2, 4, 128, false>(sb, SM_WLO, 0, m0, n0o, lane, acc);
        __syncthreads();             // everyone done with W_HI -> reuse as staging

        // stage coeffs into W_HI region: [pt][65 f32]
        const int r  = lane >> 2;
        const int c2 = (lane & 3) * 2;
        #pragma unroll
        for (int m = 0; m < 2; m++)
            #pragma unroll
            for (int n = 0; n < 4; n++) {
                int col = n0o + 8 * n + c2;
                #pragma unroll
                for (int h = 0; h < 2; h++) {
                    int row = m0 + 16 * m + r + 8 * h;
                    float* dst = (float*)(smem + SM_WHI) + row * 65 + col;
                    dst[0] = acc[m][n][2 * h + 0];
                    dst[1] = acc[m][n][2 * h + 1];
                }
            }
        __syncthreads();

        // contraction with Chebyshev basis (threads 0..127, thread = point)
        if (tid < PTS) {
            float ch[16];
            #pragma unroll
            for (int o = 0; o < 16; o++) ch[o] = *(float*)(smem + SM_CHEB + tid * 68 + o * 4);
            const float* cf = (float*)(smem + SM_WHI) + tid * 65;
            const int pt = blockIdx.x * PTS + tid;
            #pragma unroll
            for (int f = 0; f < 3; f++) {
                float sum = 0.0f;
                #pragma unroll
                for (int o = 0; o < 16; o++)
                    sum += (cf[f * 16 + o] + __ldg(bout + f * 16 + o)) * ch[o];
                out[pt * 3 + f] = sum;
            }
        }
    }
}

// ---------------- launch ----------------
extern "C" void kernel_launch(void* const* d_in, const int* in_sizes, int n_in,
                              void* d_out, int out_size)
{
    const float* x      = (const float*)d_in[0];
    const float* view   = (const float*)d_in[1];
    const float* normal = (const float*)d_in[2];
    const float* light  = (const float*)d_in[3];
    const float* W0     = (const float*)d_in[4];
    const float* b0     = (const float*)d_in[5];
    const float* Wh     = (const float*)d_in[6];
    const float* bh     = (const float*)d_in[7];
    const float* Wout   = (const float*)d_in[8];
    const float* bout   = (const float*)d_in[9];
    float* out = (float*)d_out;

    convert_weights_kernel<<<544, 256>>>(W0, b0, Wh, bh, Wout);

    cudaFuncSetAttribute(fourier_mma_kernel,
                         cudaFuncAttributeMaxDynamicSharedMemorySize, (int)SM_TOTAL);
    fourier_mma_kernel<<<NBLK, TPB, SM_TOTAL>>>(x, view, normal, light, bout, out);
}

// round 10
// speedup vs baseline: 1.2520x; 1.1019x over previous
#include <cuda_runtime.h>
#include <cuda_bf16.h>
#include <math.h>
#include <stdint.h>

#define TPB   128
#define PTS   64
#define NBLK  4096

// ---------------- smem layout (bytes), per CTA (~100.3 KB -> 2 CTAs/SM) ----------------
#define SM_AHI  0u            // A hi: 64 pts x 384B (192 bf16: h[0..127], enc[128..190], bias)
#define SM_ALO  24576u        // A lo
#define SM_W0   49152u        // weight ring buffer 0 (24576B)
#define SM_W1   73728u        // weight ring buffer 1
#define SM_CHEB 98304u        // 64 x 68B
#define SM_MBAR 102656u       // 2 mbarriers
#define SM_TOTAL 102688u

// ---------------- global weight scratch (pre-swizzled smem images) ----------------
#define IMG_L0  0u
#define P_L0    16384u        // 64 rows x 256B
#define P_HID   49152u        // 192 rows x 256B (= chunks hi0,hi1 of 24576; lo0,lo1 follow)
#define CHUNK_H 24576u
#define IMG_HID(l) (32768u + (uint32_t)((l) - 1) * 98304u)   // l = 1..5
#define IMG_OUT 524288u
#define P_OUT   16384u        // 128 rows x 128B (N padded to 64)
__device__ __align__(16) unsigned char g_wscratch[557056];

// ---------------- PTX helpers ----------------
__device__ __forceinline__ uint32_t smem_u32(const void* p) {
    uint32_t a;
    asm("{ .reg .u64 t; cvta.to.shared.u64 t, %1; cvt.u32.u64 %0, t; }" : "=r"(a) : "l"(p));
    return a;
}
__device__ __forceinline__ void ldsm_x4(uint32_t& r0, uint32_t& r1, uint32_t& r2, uint32_t& r3, uint32_t a) {
    asm volatile("ldmatrix.sync.aligned.m8n8.x4.shared.b16 {%0,%1,%2,%3}, [%4];"
        : "=r"(r0), "=r"(r1), "=r"(r2), "=r"(r3) : "r"(a));
}
__device__ __forceinline__ void ldsm_x4t(uint32_t& r0, uint32_t& r1, uint32_t& r2, uint32_t& r3, uint32_t a) {
    asm volatile("ldmatrix.sync.aligned.m8n8.x4.trans.shared.b16 {%0,%1,%2,%3}, [%4];"
        : "=r"(r0), "=r"(r1), "=r"(r2), "=r"(r3) : "r"(a));
}
__device__ __forceinline__ void mma_bf16(float* d, uint32_t a0, uint32_t a1, uint32_t a2, uint32_t a3,
                                         uint32_t b0, uint32_t b1) {
    asm volatile("mma.sync.aligned.m16n8k16.row.col.f32.bf16.bf16.f32 "
        "{%0,%1,%2,%3}, {%4,%5,%6,%7}, {%8,%9}, {%0,%1,%2,%3};"
        : "+f"(d[0]), "+f"(d[1]), "+f"(d[2]), "+f"(d[3])
        : "r"(a0), "r"(a1), "r"(a2), "r"(a3), "r"(b0), "r"(b1));
}
#define MBARRIER_INIT(mb, c) asm volatile("mbarrier.init.shared.b64 [%0], %1;" :: "r"((uint32_t)(mb)), "r"((uint32_t)(c)) : "memory")
#define MBAR_WAIT(mb, par) do {                                                     \
    uint32_t _mb = (uint32_t)(mb), _p = (uint32_t)(par);                            \
    asm volatile("{\n\t.reg .pred P1;\n\tWL_%=:\n\t"                                \
        "mbarrier.try_wait.parity.acquire.cta.shared::cta.b64 P1, [%0], %1, 0x989680;\n\t" \
        "@P1 bra.uni WD_%=;\n\tbra.uni WL_%=;\n\tWD_%=:\n\t}"                       \
        :: "r"(_mb), "r"(_p) : "memory");                                           \
} while (0)
// one-thread weight fetch: expect_tx + bulk async copy (zero warp issue cost)
__device__ __forceinline__ void w_fetch(uint32_t mb, uint32_t sdst, const unsigned char* gsrc, uint32_t bytes) {
    asm volatile("mbarrier.arrive.expect_tx.shared.b64 _, [%0], %1;"
        :: "r"(mb), "r"(bytes) : "memory");
    asm volatile("cp.async.bulk.shared::cluster.global.mbarrier::complete_tx::bytes [%0], [%1], %2, [%3];"
        :: "r"(sdst), "l"(gsrc), "r"(bytes), "r"(mb) : "memory");
}
__device__ __host__ __forceinline__ uint32_t swz_off(uint32_t row, uint32_t cb, uint32_t rowB) {
    return row * rowB + (cb & ~127u) + ((cb & 127u) ^ ((row & 7u) << 4));
}

// ---------------- weight converter (unchanged layout) ----------------
__global__ void convert_weights_kernel(const float* __restrict__ W0, const float* __restrict__ b0,
                                       const float* __restrict__ Wh, const float* __restrict__ bh,
                                       const float* __restrict__ Wout)
{
    int idx = blockIdx.x * blockDim.x + threadIdx.x;
    if (idx >= 139264) return;
    float w; uint32_t img, part, rowB, k, n;
    if (idx < 8192) {                       // L0: K=64 (row 63 = bias), N=128
        k = (uint32_t)(idx >> 7); n = (uint32_t)(idx & 127);
        img = IMG_L0; part = P_L0; rowB = 256;
        w = (k < 63) ? W0[k * 128 + n] : b0[n];
    } else if (idx < 131072) {              // hidden: K=192 (row 191 = bias), N=128
        int t = idx - 8192; int l = t / 24576; int r = t % 24576;
        k = (uint32_t)(r >> 7); n = (uint32_t)(r & 127);
        img = IMG_HID(l + 1); part = P_HID; rowB = 256;
        w = (k < 191) ? Wh[((uint32_t)l * 191 + k) * 128 + n] : bh[l * 128 + n];
    } else {                                // out: K=128, N=48 padded to 64
        int t = idx - 131072;
        k = (uint32_t)(t >> 6); n = (uint32_t)(t & 63);
        img = IMG_OUT; part = P_OUT; rowB = 128;
        w = (n < 48) ? Wout[k * 48 + n] : 0.0f;
    }
    __nv_bfloat16 hi = __float2bfloat16(w);
    __nv_bfloat16 lo = __float2bfloat16(w - __bfloat162float(hi));
    uint32_t off = swz_off(k, n * 2, rowB);
    *(__nv_bfloat16*)(g_wscratch + img + off)        = hi;
    *(__nv_bfloat16*)(g_wscratch + img + part + off) = lo;
}

// ---------------- small math utils ----------------
__device__ __forceinline__ float3 norm3(float3 v, float eps) {
    float n = sqrtf(v.x * v.x + v.y * v.y + v.z * v.z);
    float inv = 1.0f / fmaxf(n, eps);
    return make_float3(v.x * inv, v.y * inv, v.z * inv);
}
__device__ __forceinline__ float3 cross3(float3 a, float3 b) {
    return make_float3(a.y * b.z - a.z * b.y, a.z * b.x - a.x * b.z, a.x * b.y - a.y * b.x);
}
__device__ __forceinline__ uint32_t packbf(float a, float b) {
    __nv_bfloat162 p; p.x = __float2bfloat16(a); p.y = __float2bfloat16(b);
    return *(uint32_t*)&p;
}

// ---------------- MMA pass over one weight CHUNK ----------------
// W chunk: KSTEPS*16 rows x (ROWB) bytes swizzled at wreg (local row = 16s+l15).
// A cols for kstep s = kbaseA + 16s. Warp: rows [m0,m0+16*MT) x cols [n0,n0+8*NT).
template<int KSTEPS, int MT, int NT, int ROWB, bool DUAL>
__device__ __forceinline__ void mma_pass(uint32_t sb, uint32_t wreg, int kbaseA,
                                         int m0, int n0, int lane, float (&acc)[MT][NT][4])
{
    const uint32_t l15 = (uint32_t)(lane & 15);
    const uint32_t lh  = (uint32_t)(lane >> 4);
    #pragma unroll
    for (int s = 0; s < KSTEPS; s++) {
        uint32_t b[NT][2];
        #pragma unroll
        for (int t = 0; t < NT / 2; t++) {
            uint32_t krow = (uint32_t)(16 * s) + l15;
            uint32_t cb = (uint32_t)(n0 * 2 + t * 32) + (lh << 4);
            uint32_t off = swz_off(krow, cb, (uint32_t)ROWB);
            ldsm_x4t(b[2 * t][0], b[2 * t][1], b[2 * t + 1][0], b[2 * t + 1][1], sb + wreg + off);
        }
        const uint32_t cbA = (uint32_t)((kbaseA + 16 * s) * 2) + (lh << 4);
        #pragma unroll
        for (int m = 0; m < MT; m++) {
            uint32_t row = (uint32_t)(m0 + 16 * m) + l15;
            uint32_t off = swz_off(row, cbA, 384u);
            uint32_t a0, a1, a2, a3;
            ldsm_x4(a0, a1, a2, a3, sb + SM_AHI + off);
            #pragma unroll
            for (int n = 0; n < NT; n++) mma_bf16(acc[m][n], a0, a1, a2, a3, b[n][0], b[n][1]);
            if (DUAL) {
                ldsm_x4(a0, a1, a2, a3, sb + SM_ALO + off);
                #pragma unroll
                for (int n = 0; n < NT; n++) mma_bf16(acc[m][n], a0, a1, a2, a3, b[n][0], b[n][1]);
            }
        }
    }
}

// hidden-layer epilogue: leaky-relu, split hi/lo, store into A h-region
__device__ __forceinline__ void epilogue_store(unsigned char* smem, float (&acc)[2][8][4],
                                               int lane, int m0, int n0)
{
    const int r  = lane >> 2;
    const int c2 = (lane & 3) * 2;
    #pragma unroll
    for (int m = 0; m < 2; m++)
        #pragma unroll
        for (int n = 0; n < 8; n++) {
            const uint32_t cb = (uint32_t)((n0 + 8 * n + c2) * 2);
            #pragma unroll
            for (int h = 0; h < 2; h++) {
                uint32_t row = (uint32_t)(m0 + 16 * m + r + 8 * h);
                float v0 = acc[m][n][2 * h + 0];
                float v1 = acc[m][n][2 * h + 1];
                v0 = v0 > 0.0f ? v0 : 0.01f * v0;
                v1 = v1 > 0.0f ? v1 : 0.01f * v1;
                __nv_bfloat16 h0 = __float2bfloat16(v0), h1 = __float2bfloat16(v1);
                float l0 = v0 - __bfloat162float(h0), l1 = v1 - __bfloat162float(h1);
                __nv_bfloat162 hp; hp.x = h0; hp.y = h1;
                uint32_t off = swz_off(row, cb, 384u);
                *(uint32_t*)(smem + SM_AHI + off) = *(uint32_t*)&hp;
                *(uint32_t*)(smem + SM_ALO + off) = packbf(l0, l1);
            }
        }
}

// ---------------- main kernel ----------------
extern "C" __global__ void __launch_bounds__(TPB, 2)
fourier_mma_kernel(const float* __restrict__ x, const float* __restrict__ view,
                   const float* __restrict__ normal, const float* __restrict__ light,
                   const float* __restrict__ bout, float* __restrict__ out)
{
    extern __shared__ __align__(16) unsigned char smem[];
    const uint32_t sb = smem_u32(smem);
    const uint32_t mb0 = sb + SM_MBAR;
    const uint32_t mb1 = sb + SM_MBAR + 8;
    const int tid  = threadIdx.x;
    const int lane = tid & 31;
    const int warp = tid >> 5;

    // init mbarriers + kick off L0 weight fetches (single thread, async engine)
    if (tid == 0) {
        MBARRIER_INIT(mb0, 1);
        MBARRIER_INIT(mb1, 1);
        w_fetch(mb0, sb + SM_W0, g_wscratch + IMG_L0, P_L0);
        w_fetch(mb1, sb + SM_W1, g_wscratch + IMG_L0 + P_L0, P_L0);
    }

    // ---- geometry + Chebyshev + Fourier encoding (threads 0..63, thread = point) ----
    if (tid < PTS) {
        const int pt = blockIdx.x * PTS + tid;
        float3 xx = make_float3(x[pt * 3 + 0], x[pt * 3 + 1], x[pt * 3 + 2]);
        float3 vv = make_float3(view[pt * 3 + 0], view[pt * 3 + 1], view[pt * 3 + 2]);
        float3 nn = make_float3(normal[pt * 3 + 0], normal[pt * 3 + 1], normal[pt * 3 + 2]);
        float3 ll = make_float3(light[pt * 3 + 0], light[pt * 3 + 1], light[pt * 3 + 2]);

        float3 n = norm3(nn, 1e-6f);
        float sgn = (n.z >= 0.0f) ? 1.0f : -1.0f;
        float s_z = sgn + n.z;
        float safe = (fabsf(s_z) < 1e-6f) ? copysignf(1e-6f, s_z) : s_z;
        float a = -1.0f / safe;
        float b = n.x * n.y * a;
        float3 s = make_float3(n.x * n.x * a * sgn + 1.0f, b * sgn, -n.x * sgn);
        s = norm3(s, 1e-6f);
        float3 t = norm3(cross3(s, n), 1e-6f);
        s = norm3(cross3(n, t), 1e-6f);

        float3 v = norm3(vv, 1e-6f);
        float3 wo = norm3(make_float3(v.x * s.x + v.y * s.y + v.z * s.z,
                                      v.x * t.x + v.y * t.y + v.z * t.z,
                                      v.x * n.x + v.y * n.y + v.z * n.z), 1e-7f);
        float3 wi = norm3(make_float3(ll.x * s.x + ll.y * s.y + ll.z * s.z,
                                      ll.x * t.x + ll.y * t.y + ll.z * t.z,
                                      ll.x * n.x + ll.y * n.y + ll.z * n.z), 1e-7f);
        float num = -(wi.x * wo.x + wi.y * wo.y);
        float den = sqrtf((wo.x * wo.x + wo.y * wo.y) * (wi.x * wi.x + wi.y * wi.y));
        float cp = fminf(1.0f, fmaxf(-1.0f, num / den));

        float c0 = 1.0f, c1 = cp;
        *(float*)(smem + SM_CHEB + tid * 68 + 0) = c0;
        *(float*)(smem + SM_CHEB + tid * 68 + 4) = c1;
        #pragma unroll
        for (int o = 2; o < 16; o++) {
            float c2v = 2.0f * cp * c1 - c0;
            *(float*)(smem + SM_CHEB + tid * 68 + o * 4) = c2v;
            c0 = c1; c1 = c2v;
        }

        float enc[64];
        enc[0] = xx.x; enc[1] = xx.y; enc[2] = xx.z;
        float fr = 1.0f;
        #pragma unroll
        for (int f = 0; f < 10; f++) {
            float sv, cv;
            sincosf(xx.x * fr, &sv, &cv); enc[3 + f * 3 + 0] = sv; enc[33 + f * 3 + 0] = cv;
            sincosf(xx.y * fr, &sv, &cv); enc[3 + f * 3 + 1] = sv; enc[33 + f * 3 + 1] = cv;
            sincosf(xx.z * fr, &sv, &cv); enc[3 + f * 3 + 2] = sv; enc[33 + f * 3 + 2] = cv;
            fr *= 2.0f;
        }
        enc[63] = 1.0f;                      // bias slot

        #pragma unroll
        for (int j = 0; j < 32; j++) {
            float e0 = enc[2 * j], e1 = enc[2 * j + 1];
            __nv_bfloat16 h0 = __float2bfloat16(e0), h1 = __float2bfloat16(e1);
            float l0 = e0 - __bfloat162float(h0), l1 = e1 - __bfloat162float(h1);
            __nv_bfloat162 hp; hp.x = h0; hp.y = h1;
            uint32_t off = swz_off((uint32_t)tid, 256u + 4u * (uint32_t)j, 384u);
            *(uint32_t*)(smem + SM_AHI + off) = *(uint32_t*)&hp;
            *(uint32_t*)(smem + SM_ALO + off) = packbf(l0, l1);
        }
    }
    __syncthreads();          // A/cheb + mbarrier init visible
    int ph0 = 0, ph1 = 0;

    // warp tiling: 2 m-groups (32 pts) x 2 n-groups
    const int mg = warp >> 1;        // 0..1
    const int ng = warp & 1;         // 0..1
    const int m0 = mg * 32;
    const int n0h = ng * 64;         // hidden layers: 64 cols per warp

    // ================= layer 0 (K=64, A cols 128..191) =================
    {
        MBAR_WAIT(mb0, ph0); ph0 ^= 1;      // W_hi(L0) landed in W0
        float acc[2][8][4] = {};
        mma_pass<4, 2, 8, 256, true>(sb, SM_W0, 128, m0, n0h, lane, acc);
        __syncthreads();
        if (tid == 0) w_fetch(mb0, sb + SM_W0, g_wscratch + IMG_HID(1) + 0 * CHUNK_H, CHUNK_H);
        MBAR_WAIT(mb1, ph1); ph1 ^= 1;      // W_lo(L0) in W1
        mma_pass<4, 2, 8, 256, false>(sb, SM_W1, 128, m0, n0h, lane, acc);
        __syncthreads();
        if (tid == 0) w_fetch(mb1, sb + SM_W1, g_wscratch + IMG_HID(1) + 1 * CHUNK_H, CHUNK_H);
        epilogue_store(smem, acc, lane, m0, n0h);
        __syncthreads();                    // A(l=1) visible
    }

    // ================= hidden layers 1..5 (K=192, 4 chunks of 96 rows) =================
    #pragma unroll 1
    for (int l = 1; l <= 5; l++) {
        const unsigned char* img  = g_wscratch + IMG_HID(l);
        const unsigned char* nimg = g_wscratch + ((l == 5) ? IMG_OUT : IMG_HID(l + 1));
        const uint32_t nsz = (l == 5) ? P_OUT : CHUNK_H;     // next chunk sizes
        float acc[2][8][4] = {};

        MBAR_WAIT(mb0, ph0); ph0 ^= 1;      // hi0 (K rows 0..95)
        mma_pass<6, 2, 8, 256, true>(sb, SM_W0, 0, m0, n0h, lane, acc);
        __syncthreads();
        if (tid == 0) w_fetch(mb0, sb + SM_W0, img + 2 * CHUNK_H, CHUNK_H);   // lo0

        MBAR_WAIT(mb1, ph1); ph1 ^= 1;      // hi1 (K rows 96..191)
        mma_pass<6, 2, 8, 256, true>(sb, SM_W1, 96, m0, n0h, lane, acc);
        __syncthreads();
        if (tid == 0) w_fetch(mb1, sb + SM_W1, img + 3 * CHUNK_H, CHUNK_H);   // lo1

        MBAR_WAIT(mb0, ph0); ph0 ^= 1;      // lo0
        mma_pass<6, 2, 8, 256, false>(sb, SM_W0, 0, m0, n0h, lane, acc);
        __syncthreads();
        if (tid == 0) w_fetch(mb0, sb + SM_W0, nimg, nsz);                    // next hi0

        MBAR_WAIT(mb1, ph1); ph1 ^= 1;      // lo1
        mma_pass<6, 2, 8, 256, false>(sb, SM_W1, 96, m0, n0h, lane, acc);
        __syncthreads();
        if (tid == 0) w_fetch(mb1, sb + SM_W1, nimg + ((l == 5) ? P_OUT : CHUNK_H), nsz); // next hi1 / out lo

        epilogue_store(smem, acc, lane, m0, n0h);
        __syncthreads();
    }

    // ================= output layer (K=128, N=64 padded) =================
    {
        const int n0o = ng * 32;     // 32 cols per warp
        MBAR_WAIT(mb0, ph0); ph0 ^= 1;      // out hi in W0
        float acc[2][4][4] = {};
        mma_pass<8, 2, 4, 128, true>(sb, SM_W0, 0, m0, n0o, lane, acc);
        MBAR_WAIT(mb1, ph1); ph1 ^= 1;      // out lo in W1
        mma_pass<8, 2, 4, 128, false>(sb, SM_W1, 0, m0, n0o, lane, acc);
        __syncthreads();             // all warps done with W0 -> reuse as staging

        // stage coeffs into W0 region: [pt][65 f32]
        const int r  = lane >> 2;
        const int c2 = (lane & 3) * 2;
        #pragma unroll
        for (int m = 0; m < 2; m++)
            #pragma unroll
            for (int n = 0; n < 4; n++) {
                int col = n0o + 8 * n + c2;
                #pragma unroll
                for (int h = 0; h < 2; h++) {
                    int row = m0 + 16 * m + r + 8 * h;
                    float* dst = (float*)(smem + SM_W0) + row * 65 + col;
                    dst[0] = acc[m][n][2 * h + 0];
                    dst[1] = acc[m][n][2 * h + 1];
                }
            }
        __syncthreads();

        // contraction with Chebyshev basis (threads 0..63, thread = point)
        if (tid < PTS) {
            float ch[16];
            #pragma unroll
            for (int o = 0; o < 16; o++) ch[o] = *(float*)(smem + SM_CHEB + tid * 68 + o * 4);
            const float* cf = (float*)(smem + SM_W0) + tid * 65;
            const int pt = blockIdx.x * PTS + tid;
            #pragma unroll
            for (int f = 0; f < 3; f++) {
                float sum = 0.0f;
                #pragma unroll
                for (int o = 0; o < 16; o++)
                    sum += (cf[f * 16 + o] + __ldg(bout + f * 16 + o)) * ch[o];
                out[pt * 3 + f] = sum;
            }
        }
    }
}

// ---------------- launch ----------------
extern "C" void kernel_launch(void* const* d_in, const int* in_sizes, int n_in,
                              void* d_out, int out_size)
{
    const float* x      = (const float*)d_in[0];
    const float* view   = (const float*)d_in[1];
    const float* normal = (const float*)d_in[2];
    const float* light  = (const float*)d_in[3];
    const float* W0     = (const float*)d_in[4];
    const float* b0     = (const float*)d_in[5];
    const float* Wh     = (const float*)d_in[6];
    const float* bh     = (const float*)d_in[7];
    const float* Wout   = (const float*)d_in[8];
    const float* bout   = (const float*)d_in[9];
    float* out = (float*)d_out;

    convert_weights_kernel<<<544, 256>>>(W0, b0, Wh, bh, Wout);

    cudaFuncSetAttribute(fourier_mma_kernel,
                         cudaFuncAttributeMaxDynamicSharedMemorySize, (int)SM_TOTAL);
    fourier_mma_kernel<<<NBLK, TPB, SM_TOTAL>>>(x, view, normal, light, bout, out);
}

// round 11
// speedup vs baseline: 1.2685x; 1.0132x over previous
#include <cuda_runtime.h>
#include <cuda_bf16.h>
#include <math.h>
#include <stdint.h>

#define TPB   128
#define PTS   64
#define NBLK  4096

// ---------------- smem layout (bytes), per CTA (~72.3 KB -> 3 CTAs/SM) ----------------
#define SM_AHI  0u            // A hi: 64 pts x 384B (192 bf16: h[0..127], enc[128..190], bias)
#define SM_ALO  24576u        // A lo
#define SM_W0   49152u        // weight ring buffer 0 (12288B)
#define SM_W1   61440u        // weight ring buffer 1
#define SM_CP   73728u        // 64 x 4B cos_phi
#define SM_MBAR 73984u        // 2 mbarriers
#define SM_TOTAL 74016u

// ---------------- global weight scratch (pre-swizzled smem images) ----------------
#define IMG_L0  0u
#define P_L0    16384u        // 64 rows x 256B
#define P_HID   49152u        // 192 rows x 256B
#define IMG_HID(l) (32768u + (uint32_t)((l) - 1) * 98304u)   // l = 1..5
#define IMG_OUT 524288u
#define P_OUT   16384u        // 128 rows x 128B (N padded to 64)
__device__ __align__(16) unsigned char g_wscratch[557056];

// chunk stream: 48 chunks total
//   id 0..3   : L0, 4 x 8192B  (hi0,hi1,lo0,lo1; 32 rows each)
//   id 4..43  : hidden l=1..5, 8 x 12288B each (hi0..hi3, lo0..lo3; 48 rows each)
//   id 44..47 : out, 4 x 8192B (hi0,hi1,lo0,lo1; 64 rows each)
__device__ __forceinline__ const unsigned char* chunk_src(int id, uint32_t& sz) {
    if (id < 4)  { sz = 8192u;  return g_wscratch + IMG_L0 + (uint32_t)id * 8192u; }
    if (id < 44) { int t = id - 4; int l = t >> 3; int c = t & 7;
                   sz = 12288u; return g_wscratch + IMG_HID(l + 1) + (uint32_t)c * 12288u; }
    sz = 8192u; return g_wscratch + IMG_OUT + (uint32_t)(id - 44) * 8192u;
}

// ---------------- PTX helpers ----------------
__device__ __forceinline__ uint32_t smem_u32(const void* p) {
    uint32_t a;
    asm("{ .reg .u64 t; cvta.to.shared.u64 t, %1; cvt.u32.u64 %0, t; }" : "=r"(a) : "l"(p));
    return a;
}
__device__ __forceinline__ void ldsm_x4(uint32_t& r0, uint32_t& r1, uint32_t& r2, uint32_t& r3, uint32_t a) {
    asm volatile("ldmatrix.sync.aligned.m8n8.x4.shared.b16 {%0,%1,%2,%3}, [%4];"
        : "=r"(r0), "=r"(r1), "=r"(r2), "=r"(r3) : "r"(a));
}
__device__ __forceinline__ void ldsm_x4t(uint32_t& r0, uint32_t& r1, uint32_t& r2, uint32_t& r3, uint32_t a) {
    asm volatile("ldmatrix.sync.aligned.m8n8.x4.trans.shared.b16 {%0,%1,%2,%3}, [%4];"
        : "=r"(r0), "=r"(r1), "=r"(r2), "=r"(r3) : "r"(a));
}
__device__ __forceinline__ void mma_bf16(float* d, uint32_t a0, uint32_t a1, uint32_t a2, uint32_t a3,
                                         uint32_t b0, uint32_t b1) {
    asm volatile("mma.sync.aligned.m16n8k16.row.col.f32.bf16.bf16.f32 "
        "{%0,%1,%2,%3}, {%4,%5,%6,%7}, {%8,%9}, {%0,%1,%2,%3};"
        : "+f"(d[0]), "+f"(d[1]), "+f"(d[2]), "+f"(d[3])
        : "r"(a0), "r"(a1), "r"(a2), "r"(a3), "r"(b0), "r"(b1));
}
#define MBARRIER_INIT(mb, c) asm volatile("mbarrier.init.shared.b64 [%0], %1;" :: "r"((uint32_t)(mb)), "r"((uint32_t)(c)) : "memory")
#define MBAR_WAIT(mb, par) do {                                                     \
    uint32_t _mb = (uint32_t)(mb), _p = (uint32_t)(par);                            \
    asm volatile("{\n\t.reg .pred P1;\n\tWL_%=:\n\t"                                \
        "mbarrier.try_wait.parity.acquire.cta.shared::cta.b64 P1, [%0], %1, 0x989680;\n\t" \
        "@P1 bra.uni WD_%=;\n\tbra.uni WL_%=;\n\tWD_%=:\n\t}"                       \
        :: "r"(_mb), "r"(_p) : "memory");                                           \
} while (0)
// one-thread weight fetch: expect_tx + bulk async copy (zero warp issue cost)
__device__ __forceinline__ void w_fetch(uint32_t mb, uint32_t sdst, const unsigned char* gsrc, uint32_t bytes) {
    asm volatile("mbarrier.arrive.expect_tx.shared.b64 _, [%0], %1;"
        :: "r"(mb), "r"(bytes) : "memory");
    asm volatile("cp.async.bulk.shared::cluster.global.mbarrier::complete_tx::bytes [%0], [%1], %2, [%3];"
        :: "r"(sdst), "l"(gsrc), "r"(bytes), "r"(mb) : "memory");
}
__device__ __host__ __forceinline__ uint32_t swz_off(uint32_t row, uint32_t cb, uint32_t rowB) {
    return row * rowB + (cb & ~127u) + ((cb & 127u) ^ ((row & 7u) << 4));
}

// ---------------- weight converter (unchanged layout) ----------------
__global__ void convert_weights_kernel(const float* __restrict__ W0, const float* __restrict__ b0,
                                       const float* __restrict__ Wh, const float* __restrict__ bh,
                                       const float* __restrict__ Wout)
{
    int idx = blockIdx.x * blockDim.x + threadIdx.x;
    if (idx >= 139264) return;
    float w; uint32_t img, part, rowB, k, n;
    if (idx < 8192) {                       // L0: K=64 (row 63 = bias), N=128
        k = (uint32_t)(idx >> 7); n = (uint32_t)(idx & 127);
        img = IMG_L0; part = P_L0; rowB = 256;
        w = (k < 63) ? W0[k * 128 + n] : b0[n];
    } else if (idx < 131072) {              // hidden: K=192 (row 191 = bias), N=128
        int t = idx - 8192; int l = t / 24576; int r = t % 24576;
        k = (uint32_t)(r >> 7); n = (uint32_t)(r & 127);
        img = IMG_HID(l + 1); part = P_HID; rowB = 256;
        w = (k < 191) ? Wh[((uint32_t)l * 191 + k) * 128 + n] : bh[l * 128 + n];
    } else {                                // out: K=128, N=48 padded to 64
        int t = idx - 131072;
        k = (uint32_t)(t >> 6); n = (uint32_t)(t & 63);
        img = IMG_OUT; part = P_OUT; rowB = 128;
        w = (n < 48) ? Wout[k * 48 + n] : 0.0f;
    }
    __nv_bfloat16 hi = __float2bfloat16(w);
    __nv_bfloat16 lo = __float2bfloat16(w - __bfloat162float(hi));
    uint32_t off = swz_off(k, n * 2, rowB);
    *(__nv_bfloat16*)(g_wscratch + img + off)        = hi;
    *(__nv_bfloat16*)(g_wscratch + img + part + off) = lo;
}

// ---------------- small math utils ----------------
__device__ __forceinline__ float3 norm3(float3 v, float eps) {
    float n = sqrtf(v.x * v.x + v.y * v.y + v.z * v.z);
    float inv = 1.0f / fmaxf(n, eps);
    return make_float3(v.x * inv, v.y * inv, v.z * inv);
}
__device__ __forceinline__ float3 cross3(float3 a, float3 b) {
    return make_float3(a.y * b.z - a.z * b.y, a.z * b.x - a.x * b.z, a.x * b.y - a.y * b.x);
}
__device__ __forceinline__ uint32_t packbf(float a, float b) {
    __nv_bfloat162 p; p.x = __float2bfloat16(a); p.y = __float2bfloat16(b);
    return *(uint32_t*)&p;
}

// ---------------- MMA pass over one weight CHUNK ----------------
template<int KSTEPS, int MT, int NT, int ROWB, bool DUAL>
__device__ __forceinline__ void mma_pass(uint32_t sb, uint32_t wreg, int kbaseA,
                                         int m0, int n0, int lane, float (&acc)[MT][NT][4])
{
    const uint32_t l15 = (uint32_t)(lane & 15);
    const uint32_t lh  = (uint32_t)(lane >> 4);
    #pragma unroll
    for (int s = 0; s < KSTEPS; s++) {
        uint32_t b[NT][2];
        #pragma unroll
        for (int t = 0; t < NT / 2; t++) {
            uint32_t krow = (uint32_t)(16 * s) + l15;
            uint32_t cb = (uint32_t)(n0 * 2 + t * 32) + (lh << 4);
            uint32_t off = swz_off(krow, cb, (uint32_t)ROWB);
            ldsm_x4t(b[2 * t][0], b[2 * t][1], b[2 * t + 1][0], b[2 * t + 1][1], sb + wreg + off);
        }
        const uint32_t cbA = (uint32_t)((kbaseA + 16 * s) * 2) + (lh << 4);
        #pragma unroll
        for (int m = 0; m < MT; m++) {
            uint32_t row = (uint32_t)(m0 + 16 * m) + l15;
            uint32_t off = swz_off(row, cbA, 384u);
            uint32_t a0, a1, a2, a3;
            ldsm_x4(a0, a1, a2, a3, sb + SM_AHI + off);
            #pragma unroll
            for (int n = 0; n < NT; n++) mma_bf16(acc[m][n], a0, a1, a2, a3, b[n][0], b[n][1]);
            if (DUAL) {
                ldsm_x4(a0, a1, a2, a3, sb + SM_ALO + off);
                #pragma unroll
                for (int n = 0; n < NT; n++) mma_bf16(acc[m][n], a0, a1, a2, a3, b[n][0], b[n][1]);
            }
        }
    }
}

// hidden-layer epilogue: leaky-relu, split hi/lo, store into A h-region
__device__ __forceinline__ void epilogue_store(unsigned char* smem, float (&acc)[2][8][4],
                                               int lane, int m0, int n0)
{
    const int r  = lane >> 2;
    const int c2 = (lane & 3) * 2;
    #pragma unroll
    for (int m = 0; m < 2; m++)
        #pragma unroll
        for (int n = 0; n < 8; n++) {
            const uint32_t cb = (uint32_t)((n0 + 8 * n + c2) * 2);
            #pragma unroll
            for (int h = 0; h < 2; h++) {
                uint32_t row = (uint32_t)(m0 + 16 * m + r + 8 * h);
                float v0 = acc[m][n][2 * h + 0];
                float v1 = acc[m][n][2 * h + 1];
                v0 = v0 > 0.0f ? v0 : 0.01f * v0;
                v1 = v1 > 0.0f ? v1 : 0.01f * v1;
                __nv_bfloat16 h0 = __float2bfloat16(v0), h1 = __float2bfloat16(v1);
                float l0 = v0 - __bfloat162float(h0), l1 = v1 - __bfloat162float(h1);
                __nv_bfloat162 hp; hp.x = h0; hp.y = h1;
                uint32_t off = swz_off(row, cb, 384u);
                *(uint32_t*)(smem + SM_AHI + off) = *(uint32_t*)&hp;
                *(uint32_t*)(smem + SM_ALO + off) = packbf(l0, l1);
            }
        }
}

// ---------------- main kernel ----------------
extern "C" __global__ void __launch_bounds__(TPB, 3)
fourier_mma_kernel(const float* __restrict__ x, const float* __restrict__ view,
                   const float* __restrict__ normal, const float* __restrict__ light,
                   const float* __restrict__ bout, float* __restrict__ out)
{
    extern __shared__ __align__(16) unsigned char smem[];
    const uint32_t sb = smem_u32(smem);
    const uint32_t mb0 = sb + SM_MBAR;
    const uint32_t mb1 = sb + SM_MBAR + 8;
    const int tid  = threadIdx.x;
    const int lane = tid & 31;
    const int warp = tid >> 5;

    // init mbarriers + kick off first two chunk fetches
    if (tid == 0) {
        MBARRIER_INIT(mb0, 1);
        MBARRIER_INIT(mb1, 1);
        uint32_t s0, s1;
        const unsigned char* p0 = chunk_src(0, s0);
        const unsigned char* p1 = chunk_src(1, s1);
        w_fetch(mb0, sb + SM_W0, p0, s0);
        w_fetch(mb1, sb + SM_W1, p1, s1);
    }

    // ---- geometry + cos_phi + Fourier encoding (threads 0..63, thread = point) ----
    if (tid < PTS) {
        const int pt = blockIdx.x * PTS + tid;
        float3 xx = make_float3(x[pt * 3 + 0], x[pt * 3 + 1], x[pt * 3 + 2]);
        float3 vv = make_float3(view[pt * 3 + 0], view[pt * 3 + 1], view[pt * 3 + 2]);
        float3 nn = make_float3(normal[pt * 3 + 0], normal[pt * 3 + 1], normal[pt * 3 + 2]);
        float3 ll = make_float3(light[pt * 3 + 0], light[pt * 3 + 1], light[pt * 3 + 2]);

        float3 n = norm3(nn, 1e-6f);
        float sgn = (n.z >= 0.0f) ? 1.0f : -1.0f;
        float s_z = sgn + n.z;
        float safe = (fabsf(s_z) < 1e-6f) ? copysignf(1e-6f, s_z) : s_z;
        float a = -1.0f / safe;
        float b = n.x * n.y * a;
        float3 s = make_float3(n.x * n.x * a * sgn + 1.0f, b * sgn, -n.x * sgn);
        s = norm3(s, 1e-6f);
        float3 t = norm3(cross3(s, n), 1e-6f);
        s = norm3(cross3(n, t), 1e-6f);

        float3 v = norm3(vv, 1e-6f);
        float3 wo = norm3(make_float3(v.x * s.x + v.y * s.y + v.z * s.z,
                                      v.x * t.x + v.y * t.y + v.z * t.z,
                                      v.x * n.x + v.y * n.y + v.z * n.z), 1e-7f);
        float3 wi = norm3(make_float3(ll.x * s.x + ll.y * s.y + ll.z * s.z,
                                      ll.x * t.x + ll.y * t.y + ll.z * t.z,
                                      ll.x * n.x + ll.y * n.y + ll.z * n.z), 1e-7f);
        float num = -(wi.x * wo.x + wi.y * wo.y);
        float den = sqrtf((wo.x * wo.x + wo.y * wo.y) * (wi.x * wi.x + wi.y * wi.y));
        float cp = fminf(1.0f, fmaxf(-1.0f, num / den));
        *(float*)(smem + SM_CP + tid * 4) = cp;

        float enc[64];
        enc[0] = xx.x; enc[1] = xx.y; enc[2] = xx.z;
        float fr = 1.0f;
        #pragma unroll
        for (int f = 0; f < 10; f++) {
            float sv, cv;
            sincosf(xx.x * fr, &sv, &cv); enc[3 + f * 3 + 0] = sv; enc[33 + f * 3 + 0] = cv;
            sincosf(xx.y * fr, &sv, &cv); enc[3 + f * 3 + 1] = sv; enc[33 + f * 3 + 1] = cv;
            sincosf(xx.z * fr, &sv, &cv); enc[3 + f * 3 + 2] = sv; enc[33 + f * 3 + 2] = cv;
            fr *= 2.0f;
        }
        enc[63] = 1.0f;                      // bias slot

        #pragma unroll
        for (int j = 0; j < 32; j++) {
            float e0 = enc[2 * j], e1 = enc[2 * j + 1];
            __nv_bfloat16 h0 = __float2bfloat16(e0), h1 = __float2bfloat16(e1);
            float l0 = e0 - __bfloat162float(h0), l1 = e1 - __bfloat162float(h1);
            __nv_bfloat162 hp; hp.x = h0; hp.y = h1;
            uint32_t off = swz_off((uint32_t)tid, 256u + 4u * (uint32_t)j, 384u);
            *(uint32_t*)(smem + SM_AHI + off) = *(uint32_t*)&hp;
            *(uint32_t*)(smem + SM_ALO + off) = packbf(l0, l1);
        }
    }
    __syncthreads();          // A/cp + mbarrier init visible
    uint32_t ph0 = 0, ph1 = 0;
    int fid = 2;              // next chunk to fetch

    // warp tiling: 2 m-groups (32 pts) x 2 n-groups
    const int mg = warp >> 1;
    const int ng = warp & 1;
    const int m0 = mg * 32;
    const int n0h = ng * 64;

    // ================= layer 0: chunks 0..3 (32 rows each; hi,hi,lo,lo) =================
    {
        float acc[2][8][4] = {};
        #pragma unroll
        for (int c = 0; c < 4; c++) {
            const uint32_t wreg = (c & 1) ? SM_W1 : SM_W0;
            if (c & 1) { MBAR_WAIT(mb1, ph1); ph1 ^= 1; } else { MBAR_WAIT(mb0, ph0); ph0 ^= 1; }
            if (c < 2) mma_pass<2, 2, 8, 256, true >(sb, wreg, 128 + 32 * c,       m0, n0h, lane, acc);
            else       mma_pass<2, 2, 8, 256, false>(sb, wreg, 128 + 32 * (c - 2), m0, n0h, lane, acc);
            __syncthreads();
            if (tid == 0) { uint32_t s; const unsigned char* p = chunk_src(fid, s);
                            w_fetch((c & 1) ? mb1 : mb0, sb + wreg, p, s); }
            fid++;
        }
        epilogue_store(smem, acc, lane, m0, n0h);
        __syncthreads();
    }

    // ================= hidden layers 1..5: 8 chunks each (48 rows; hi x4, lo x4) =================
    #pragma unroll 1
    for (int l = 1; l <= 5; l++) {
        float acc[2][8][4] = {};
        #pragma unroll
        for (int c = 0; c < 8; c++) {
            const uint32_t wreg = (c & 1) ? SM_W1 : SM_W0;
            if (c & 1) { MBAR_WAIT(mb1, ph1); ph1 ^= 1; } else { MBAR_WAIT(mb0, ph0); ph0 ^= 1; }
            if (c < 4) mma_pass<3, 2, 8, 256, true >(sb, wreg, 48 * c,       m0, n0h, lane, acc);
            else       mma_pass<3, 2, 8, 256, false>(sb, wreg, 48 * (c - 4), m0, n0h, lane, acc);
            __syncthreads();
            if (tid == 0) { uint32_t s; const unsigned char* p = chunk_src(fid, s);
                            w_fetch((c & 1) ? mb1 : mb0, sb + wreg, p, s); }
            fid++;
        }
        epilogue_store(smem, acc, lane, m0, n0h);
        __syncthreads();
    }

    // ================= output layer: chunks 44..47 (64 rows each; hi,hi,lo,lo) =================
    {
        const int n0o = ng * 32;
        float acc[2][4][4] = {};
        #pragma unroll
        for (int c = 0; c < 4; c++) {
            const uint32_t wreg = (c & 1) ? SM_W1 : SM_W0;
            if (c & 1) { MBAR_WAIT(mb1, ph1); ph1 ^= 1; } else { MBAR_WAIT(mb0, ph0); ph0 ^= 1; }
            if (c < 2) mma_pass<4, 2, 4, 128, true >(sb, wreg, 64 * c,       m0, n0o, lane, acc);
            else       mma_pass<4, 2, 4, 128, false>(sb, wreg, 64 * (c - 2), m0, n0o, lane, acc);
            __syncthreads();
            if (tid == 0 && fid < 48) { uint32_t s; const unsigned char* p = chunk_src(fid, s);
                                        w_fetch((c & 1) ? mb1 : mb0, sb + wreg, p, s); }
            fid++;
        }

        // stage coeffs into (now dead) A_hi region: [pt][65 f32]
        const int r  = lane >> 2;
        const int c2 = (lane & 3) * 2;
        #pragma unroll
        for (int m = 0; m < 2; m++)
            #pragma unroll
            for (int n = 0; n < 4; n++) {
                int col = n0o + 8 * n + c2;
                #pragma unroll
                for (int h = 0; h < 2; h++) {
                    int row = m0 + 16 * m + r + 8 * h;
                    float* dst = (float*)(smem + SM_AHI) + row * 65 + col;
                    dst[0] = acc[m][n][2 * h + 0];
                    dst[1] = acc[m][n][2 * h + 1];
                }
            }
        __syncthreads();

        // Chebyshev contraction (threads 0..63, thread = point), cheb recomputed in regs
        if (tid < PTS) {
            float cp = *(float*)(smem + SM_CP + tid * 4);
            float ch[16];
            ch[0] = 1.0f; ch[1] = cp;
            #pragma unroll
            for (int o = 2; o < 16; o++) ch[o] = 2.0f * cp * ch[o - 1] - ch[o - 2];
            const float* cf = (float*)(smem + SM_AHI) + tid * 65;
            const int pt = blockIdx.x * PTS + tid;
            #pragma unroll
            for (int f = 0; f < 3; f++) {
                float sum = 0.0f;
                #pragma unroll
                for (int o = 0; o < 16; o++)
                    sum += (cf[f * 16 + o] + __ldg(bout + f * 16 + o)) * ch[o];
                out[pt * 3 + f] = sum;
            }
        }
    }
}

// ---------------- launch ----------------
extern "C" void kernel_launch(void* const* d_in, const int* in_sizes, int n_in,
                              void* d_out, int out_size)
{
    const float* x      = (const float*)d_in[0];
    const float* view   = (const float*)d_in[1];
    const float* normal = (const float*)d_in[2];
    const float* light  = (const float*)d_in[3];
    const float* W0     = (const float*)d_in[4];
    const float* b0     = (const float*)d_in[5];
    const float* Wh     = (const float*)d_in[6];
    const float* bh     = (const float*)d_in[7];
    const float* Wout   = (const float*)d_in[8];
    const float* bout   = (const float*)d_in[9];
    float* out = (float*)d_out;

    convert_weights_kernel<<<544, 256>>>(W0, b0, Wh, bh, Wout);

    cudaFuncSetAttribute(fourier_mma_kernel,
                         cudaFuncAttributeMaxDynamicSharedMemorySize, (int)SM_TOTAL);
    fourier_mma_kernel<<<NBLK, TPB, SM_TOTAL>>>(x, view, normal, light, bout, out);
}

// round 12
// speedup vs baseline: 1.2871x; 1.0146x over previous
#include <cuda_runtime.h>
#include <cuda_bf16.h>
#include <math.h>
#include <stdint.h>

#define TPB   128
#define PTS   64
#define NBLK  4096

// ---------------- smem layout (bytes), per CTA (~72.3 KB -> 3 CTAs/SM) ----------------
#define SM_AHI  0u            // A hi: 64 pts x 384B (192 bf16: h[0..127], enc[128..190], bias)
#define SM_ALO  24576u        // A lo
#define SM_W0   49152u        // weight ring buffer 0 (12288B)
#define SM_W1   61440u        // weight ring buffer 1
#define SM_CP   73728u        // 64 x 4B cos_phi
#define SM_MBAR 73984u        // full0, full1, empty0, empty1 (8B each)
#define SM_TOTAL 74016u

// ---------------- global weight scratch (pre-swizzled smem images) ----------------
#define IMG_L0  0u
#define P_L0    16384u        // 64 rows x 256B
#define P_HID   49152u        // 192 rows x 256B
#define IMG_HID(l) (32768u + (uint32_t)((l) - 1) * 98304u)   // l = 1..5
#define IMG_OUT 524288u
#define P_OUT   16384u        // 128 rows x 128B (N padded to 64)
__device__ __align__(16) unsigned char g_wscratch[557056];

// chunk stream: 48 chunks total
//   id 0..3   : L0, 4 x 8192B  (hi0,hi1,lo0,lo1; 32 rows each)
//   id 4..43  : hidden l=1..5, 8 x 12288B each (hi0..hi3, lo0..lo3; 48 rows each)
//   id 44..47 : out, 4 x 8192B (hi0,hi1,lo0,lo1; 64 rows each)
__device__ __forceinline__ const unsigned char* chunk_src(int id, uint32_t& sz) {
    if (id < 4)  { sz = 8192u;  return g_wscratch + IMG_L0 + (uint32_t)id * 8192u; }
    if (id < 44) { int t = id - 4; int l = t >> 3; int c = t & 7;
                   sz = 12288u; return g_wscratch + IMG_HID(l + 1) + (uint32_t)c * 12288u; }
    sz = 8192u; return g_wscratch + IMG_OUT + (uint32_t)(id - 44) * 8192u;
}

// ---------------- PTX helpers ----------------
__device__ __forceinline__ uint32_t smem_u32(const void* p) {
    uint32_t a;
    asm("{ .reg .u64 t; cvta.to.shared.u64 t, %1; cvt.u32.u64 %0, t; }" : "=r"(a) : "l"(p));
    return a;
}
__device__ __forceinline__ void ldsm_x4(uint32_t& r0, uint32_t& r1, uint32_t& r2, uint32_t& r3, uint32_t a) {
    asm volatile("ldmatrix.sync.aligned.m8n8.x4.shared.b16 {%0,%1,%2,%3}, [%4];"
        : "=r"(r0), "=r"(r1), "=r"(r2), "=r"(r3) : "r"(a));
}
__device__ __forceinline__ void ldsm_x4t(uint32_t& r0, uint32_t& r1, uint32_t& r2, uint32_t& r3, uint32_t a) {
    asm volatile("ldmatrix.sync.aligned.m8n8.x4.trans.shared.b16 {%0,%1,%2,%3}, [%4];"
        : "=r"(r0), "=r"(r1), "=r"(r2), "=r"(r3) : "r"(a));
}
__device__ __forceinline__ void mma_bf16(float* d, uint32_t a0, uint32_t a1, uint32_t a2, uint32_t a3,
                                         uint32_t b0, uint32_t b1) {
    asm volatile("mma.sync.aligned.m16n8k16.row.col.f32.bf16.bf16.f32 "
        "{%0,%1,%2,%3}, {%4,%5,%6,%7}, {%8,%9}, {%0,%1,%2,%3};"
        : "+f"(d[0]), "+f"(d[1]), "+f"(d[2]), "+f"(d[3])
        : "r"(a0), "r"(a1), "r"(a2), "r"(a3), "r"(b0), "r"(b1));
}
#define MBARRIER_INIT(mb, c) asm volatile("mbarrier.init.shared.b64 [%0], %1;" :: "r"((uint32_t)(mb)), "r"((uint32_t)(c)) : "memory")
#define MBARRIER_ARRIVE(mb) asm volatile("mbarrier.arrive.shared.b64 _, [%0];" :: "r"((uint32_t)(mb)) : "memory")
#define MBAR_WAIT(mb, par) do {                                                     \
    uint32_t _mb = (uint32_t)(mb), _p = (uint32_t)(par);                            \
    asm volatile("{\n\t.reg .pred P1;\n\tWL_%=:\n\t"                                \
        "mbarrier.try_wait.parity.acquire.cta.shared::cta.b64 P1, [%0], %1, 0x989680;\n\t" \
        "@P1 bra.uni WD_%=;\n\tbra.uni WL_%=;\n\tWD_%=:\n\t}"                       \
        :: "r"(_mb), "r"(_p) : "memory");                                           \
} while (0)
// one-thread weight fetch: expect_tx + bulk async copy (zero warp issue cost)
__device__ __forceinline__ void w_fetch(uint32_t mb, uint32_t sdst, const unsigned char* gsrc, uint32_t bytes) {
    asm volatile("mbarrier.arrive.expect_tx.shared.b64 _, [%0], %1;"
        :: "r"(mb), "r"(bytes) : "memory");
    asm volatile("cp.async.bulk.shared::cluster.global.mbarrier::complete_tx::bytes [%0], [%1], %2, [%3];"
        :: "r"(sdst), "l"(gsrc), "r"(bytes), "r"(mb) : "memory");
}
__device__ __host__ __forceinline__ uint32_t swz_off(uint32_t row, uint32_t cb, uint32_t rowB) {
    return row * rowB + (cb & ~127u) + ((cb & 127u) ^ ((row & 7u) << 4));
}

// ---------------- weight converter (unchanged layout) ----------------
__global__ void convert_weights_kernel(const float* __restrict__ W0, const float* __restrict__ b0,
                                       const float* __restrict__ Wh, const float* __restrict__ bh,
                                       const float* __restrict__ Wout)
{
    int idx = blockIdx.x * blockDim.x + threadIdx.x;
    if (idx >= 139264) return;
    float w; uint32_t img, part, rowB, k, n;
    if (idx < 8192) {                       // L0: K=64 (row 63 = bias), N=128
        k = (uint32_t)(idx >> 7); n = (uint32_t)(idx & 127);
        img = IMG_L0; part = P_L0; rowB = 256;
        w = (k < 63) ? W0[k * 128 + n] : b0[n];
    } else if (idx < 131072) {              // hidden: K=192 (row 191 = bias), N=128
        int t = idx - 8192; int l = t / 24576; int r = t % 24576;
        k = (uint32_t)(r >> 7); n = (uint32_t)(r & 127);
        img = IMG_HID(l + 1); part = P_HID; rowB = 256;
        w = (k < 191) ? Wh[((uint32_t)l * 191 + k) * 128 + n] : bh[l * 128 + n];
    } else {                                // out: K=128, N=48 padded to 64
        int t = idx - 131072;
        k = (uint32_t)(t >> 6); n = (uint32_t)(t & 63);
        img = IMG_OUT; part = P_OUT; rowB = 128;
        w = (n < 48) ? Wout[k * 48 + n] : 0.0f;
    }
    __nv_bfloat16 hi = __float2bfloat16(w);
    __nv_bfloat16 lo = __float2bfloat16(w - __bfloat162float(hi));
    uint32_t off = swz_off(k, n * 2, rowB);
    *(__nv_bfloat16*)(g_wscratch + img + off)        = hi;
    *(__nv_bfloat16*)(g_wscratch + img + part + off) = lo;
}

// ---------------- small math utils ----------------
__device__ __forceinline__ float3 norm3(float3 v, float eps) {
    float n = sqrtf(v.x * v.x + v.y * v.y + v.z * v.z);
    float inv = 1.0f / fmaxf(n, eps);
    return make_float3(v.x * inv, v.y * inv, v.z * inv);
}
__device__ __forceinline__ float3 cross3(float3 a, float3 b) {
    return make_float3(a.y * b.z - a.z * b.y, a.z * b.x - a.x * b.z, a.x * b.y - a.y * b.x);
}
__device__ __forceinline__ uint32_t packbf(float a, float b) {
    __nv_bfloat162 p; p.x = __float2bfloat16(a); p.y = __float2bfloat16(b);
    return *(uint32_t*)&p;
}

// ---------------- MMA pass over one weight CHUNK ----------------
template<int KSTEPS, int MT, int NT, int ROWB, bool DUAL>
__device__ __forceinline__ void mma_pass(uint32_t sb, uint32_t wreg, int kbaseA,
                                         int m0, int n0, int lane, float (&acc)[MT][NT][4])
{
    const uint32_t l15 = (uint32_t)(lane & 15);
    const uint32_t lh  = (uint32_t)(lane >> 4);
    #pragma unroll
    for (int s = 0; s < KSTEPS; s++) {
        uint32_t b[NT][2];
        #pragma unroll
        for (int t = 0; t < NT / 2; t++) {
            uint32_t krow = (uint32_t)(16 * s) + l15;
            uint32_t cb = (uint32_t)(n0 * 2 + t * 32) + (lh << 4);
            uint32_t off = swz_off(krow, cb, (uint32_t)ROWB);
            ldsm_x4t(b[2 * t][0], b[2 * t][1], b[2 * t + 1][0], b[2 * t + 1][1], sb + wreg + off);
        }
        const uint32_t cbA = (uint32_t)((kbaseA + 16 * s) * 2) + (lh << 4);
        #pragma unroll
        for (int m = 0; m < MT; m++) {
            uint32_t row = (uint32_t)(m0 + 16 * m) + l15;
            uint32_t off = swz_off(row, cbA, 384u);
            uint32_t a0, a1, a2, a3;
            ldsm_x4(a0, a1, a2, a3, sb + SM_AHI + off);
            #pragma unroll
            for (int n = 0; n < NT; n++) mma_bf16(acc[m][n], a0, a1, a2, a3, b[n][0], b[n][1]);
            if (DUAL) {
                ldsm_x4(a0, a1, a2, a3, sb + SM_ALO + off);
                #pragma unroll
                for (int n = 0; n < NT; n++) mma_bf16(acc[m][n], a0, a1, a2, a3, b[n][0], b[n][1]);
            }
        }
    }
}

// hidden-layer epilogue: leaky-relu, split hi/lo, store into A h-region
__device__ __forceinline__ void epilogue_store(unsigned char* smem, float (&acc)[2][8][4],
                                               int lane, int m0, int n0)
{
    const int r  = lane >> 2;
    const int c2 = (lane & 3) * 2;
    #pragma unroll
    for (int m = 0; m < 2; m++)
        #pragma unroll
        for (int n = 0; n < 8; n++) {
            const uint32_t cb = (uint32_t)((n0 + 8 * n + c2) * 2);
            #pragma unroll
            for (int h = 0; h < 2; h++) {
                uint32_t row = (uint32_t)(m0 + 16 * m + r + 8 * h);
                float v0 = acc[m][n][2 * h + 0];
                float v1 = acc[m][n][2 * h + 1];
                v0 = v0 > 0.0f ? v0 : 0.01f * v0;
                v1 = v1 > 0.0f ? v1 : 0.01f * v1;
                __nv_bfloat16 h0 = __float2bfloat16(v0), h1 = __float2bfloat16(v1);
                float l0 = v0 - __bfloat162float(h0), l1 = v1 - __bfloat162float(h1);
                __nv_bfloat162 hp; hp.x = h0; hp.y = h1;
                uint32_t off = swz_off(row, cb, 384u);
                *(uint32_t*)(smem + SM_AHI + off) = *(uint32_t*)&hp;
                *(uint32_t*)(smem + SM_ALO + off) = packbf(l0, l1);
            }
        }
}

// ---------------- main kernel ----------------
extern "C" __global__ void __launch_bounds__(TPB, 3)
fourier_mma_kernel(const float* __restrict__ x, const float* __restrict__ view,
                   const float* __restrict__ normal, const float* __restrict__ light,
                   const float* __restrict__ bout, float* __restrict__ out)
{
    extern __shared__ __align__(16) unsigned char smem[];
    const uint32_t sb = smem_u32(smem);
    const uint32_t mb0  = sb + SM_MBAR;        // full0
    const uint32_t mb1  = sb + SM_MBAR + 8;    // full1
    const uint32_t mbe0 = sb + SM_MBAR + 16;   // empty0 (count 4 = one arrive per warp)
    const uint32_t mbe1 = sb + SM_MBAR + 24;   // empty1
    const int tid  = threadIdx.x;
    const int lane = tid & 31;
    const int warp = tid >> 5;

    // init mbarriers + kick off first two chunk fetches
    if (tid == 0) {
        MBARRIER_INIT(mb0, 1);
        MBARRIER_INIT(mb1, 1);
        MBARRIER_INIT(mbe0, 4);
        MBARRIER_INIT(mbe1, 4);
        uint32_t s0, s1;
        const unsigned char* p0 = chunk_src(0, s0);
        const unsigned char* p1 = chunk_src(1, s1);
        w_fetch(mb0, sb + SM_W0, p0, s0);
        w_fetch(mb1, sb + SM_W1, p1, s1);
    }

    // ---- geometry + cos_phi + Fourier encoding (threads 0..63, thread = point) ----
    if (tid < PTS) {
        const int pt = blockIdx.x * PTS + tid;
        float3 xx = make_float3(x[pt * 3 + 0], x[pt * 3 + 1], x[pt * 3 + 2]);
        float3 vv = make_float3(view[pt * 3 + 0], view[pt * 3 + 1], view[pt * 3 + 2]);
        float3 nn = make_float3(normal[pt * 3 + 0], normal[pt * 3 + 1], normal[pt * 3 + 2]);
        float3 ll = make_float3(light[pt * 3 + 0], light[pt * 3 + 1], light[pt * 3 + 2]);

        float3 n = norm3(nn, 1e-6f);
        float sgn = (n.z >= 0.0f) ? 1.0f : -1.0f;
        float s_z = sgn + n.z;
        float safe = (fabsf(s_z) < 1e-6f) ? copysignf(1e-6f, s_z) : s_z;
        float a = -1.0f / safe;
        float b = n.x * n.y * a;
        float3 s = make_float3(n.x * n.x * a * sgn + 1.0f, b * sgn, -n.x * sgn);
        s = norm3(s, 1e-6f);
        float3 t = norm3(cross3(s, n), 1e-6f);
        s = norm3(cross3(n, t), 1e-6f);

        float3 v = norm3(vv, 1e-6f);
        float3 wo = norm3(make_float3(v.x * s.x + v.y * s.y + v.z * s.z,
                                      v.x * t.x + v.y * t.y + v.z * t.z,
                                      v.x * n.x + v.y * n.y + v.z * n.z), 1e-7f);
        float3 wi = norm3(make_float3(ll.x * s.x + ll.y * s.y + ll.z * s.z,
                                      ll.x * t.x + ll.y * t.y + ll.z * t.z,
                                      ll.x * n.x + ll.y * n.y + ll.z * n.z), 1e-7f);
        float num = -(wi.x * wo.x + wi.y * wo.y);
        float den = sqrtf((wo.x * wo.x + wo.y * wo.y) * (wi.x * wi.x + wi.y * wi.y));
        float cp = fminf(1.0f, fmaxf(-1.0f, num / den));
        *(float*)(smem + SM_CP + tid * 4) = cp;

        float enc[64];
        enc[0] = xx.x; enc[1] = xx.y; enc[2] = xx.z;
        float fr = 1.0f;
        #pragma unroll
        for (int f = 0; f < 10; f++) {
            float sv, cv;
            sincosf(xx.x * fr, &sv, &cv); enc[3 + f * 3 + 0] = sv; enc[33 + f * 3 + 0] = cv;
            sincosf(xx.y * fr, &sv, &cv); enc[3 + f * 3 + 1] = sv; enc[33 + f * 3 + 1] = cv;
            sincosf(xx.z * fr, &sv, &cv); enc[3 + f * 3 + 2] = sv; enc[33 + f * 3 + 2] = cv;
            fr *= 2.0f;
        }
        enc[63] = 1.0f;                      // bias slot

        #pragma unroll
        for (int j = 0; j < 32; j++) {
            float e0 = enc[2 * j], e1 = enc[2 * j + 1];
            __nv_bfloat16 h0 = __float2bfloat16(e0), h1 = __float2bfloat16(e1);
            float l0 = e0 - __bfloat162float(h0), l1 = e1 - __bfloat162float(h1);
            __nv_bfloat162 hp; hp.x = h0; hp.y = h1;
            uint32_t off = swz_off((uint32_t)tid, 256u + 4u * (uint32_t)j, 384u);
            *(uint32_t*)(smem + SM_AHI + off) = *(uint32_t*)&hp;
            *(uint32_t*)(smem + SM_ALO + off) = packbf(l0, l1);
        }
    }
    __syncthreads();          // A/cp + mbarrier init visible
    uint32_t ph0 = 0, ph1 = 0;   // full-barrier phases (all threads)
    uint32_t pe0 = 0, pe1 = 0;   // empty-barrier phases (used by thread 0)
    int fid = 2;                 // next chunk to fetch

    // warp tiling: 2 m-groups (32 pts) x 2 n-groups
    const int mg = warp >> 1;
    const int ng = warp & 1;
    const int m0 = mg * 32;
    const int n0h = ng * 64;

    // per-chunk bookkeeping: arrive empty, thread0 waits empty then refills buffer
    #define CHUNK_POST(c)                                                            \
        if (lane == 0) MBARRIER_ARRIVE((c & 1) ? mbe1 : mbe0);                       \
        if (tid == 0 && fid < 48) {                                                  \
            if (c & 1) { MBAR_WAIT(mbe1, pe1); pe1 ^= 1; }                           \
            else       { MBAR_WAIT(mbe0, pe0); pe0 ^= 1; }                           \
            uint32_t s; const unsigned char* p = chunk_src(fid, s);                  \
            w_fetch((c & 1) ? mb1 : mb0, sb + ((c & 1) ? SM_W1 : SM_W0), p, s);      \
        }                                                                            \
        fid++;

    // ================= layer 0: chunks 0..3 (32 rows each; hi,hi,lo,lo) =================
    {
        float acc[2][8][4] = {};
        #pragma unroll
        for (int c = 0; c < 4; c++) {
            const uint32_t wreg = (c & 1) ? SM_W1 : SM_W0;
            if (c & 1) { MBAR_WAIT(mb1, ph1); ph1 ^= 1; } else { MBAR_WAIT(mb0, ph0); ph0 ^= 1; }
            if (c < 2) mma_pass<2, 2, 8, 256, true >(sb, wreg, 128 + 32 * c,       m0, n0h, lane, acc);
            else       mma_pass<2, 2, 8, 256, false>(sb, wreg, 128 + 32 * (c - 2), m0, n0h, lane, acc);
            CHUNK_POST(c)
        }
        // L0 epilogue writes h-cols (0..255B) while L0 reads were enc-cols (256..383B):
        // disjoint -> no pre-epilogue sync needed
        epilogue_store(smem, acc, lane, m0, n0h);
        __syncthreads();
    }

    // ================= hidden layers 1..5: 8 chunks each (48 rows; hi x4, lo x4) =================
    #pragma unroll 1
    for (int l = 1; l <= 5; l++) {
        float acc[2][8][4] = {};
        #pragma unroll
        for (int c = 0; c < 8; c++) {
            const uint32_t wreg = (c & 1) ? SM_W1 : SM_W0;
            if (c & 1) { MBAR_WAIT(mb1, ph1); ph1 ^= 1; } else { MBAR_WAIT(mb0, ph0); ph0 ^= 1; }
            if (c < 4) mma_pass<3, 2, 8, 256, true >(sb, wreg, 48 * c,       m0, n0h, lane, acc);
            else       mma_pass<3, 2, 8, 256, false>(sb, wreg, 48 * (c - 4), m0, n0h, lane, acc);
            CHUNK_POST(c)
        }
        __syncthreads();       // all warps done reading A(l) before overwrite
        epilogue_store(smem, acc, lane, m0, n0h);
        __syncthreads();       // A(l+1) visible
    }

    // ================= output layer: chunks 44..47 (64 rows each; hi,hi,lo,lo) =================
    {
        const int n0o = ng * 32;
        float acc[2][4][4] = {};
        #pragma unroll
        for (int c = 0; c < 4; c++) {
            const uint32_t wreg = (c & 1) ? SM_W1 : SM_W0;
            if (c & 1) { MBAR_WAIT(mb1, ph1); ph1 ^= 1; } else { MBAR_WAIT(mb0, ph0); ph0 ^= 1; }
            if (c < 2) mma_pass<4, 2, 4, 128, true >(sb, wreg, 64 * c,       m0, n0o, lane, acc);
            else       mma_pass<4, 2, 4, 128, false>(sb, wreg, 64 * (c - 2), m0, n0o, lane, acc);
            CHUNK_POST(c)
        }
        __syncthreads();       // all warps done with A + W buffers

        // stage coeffs into (now dead) A_hi region: [pt][65 f32]
        const int r  = lane >> 2;
        const int c2 = (lane & 3) * 2;
        #pragma unroll
        for (int m = 0; m < 2; m++)
            #pragma unroll
            for (int n = 0; n < 4; n++) {
                int col = n0o + 8 * n + c2;
                #pragma unroll
                for (int h = 0; h < 2; h++) {
                    int row = m0 + 16 * m + r + 8 * h;
                    float* dst = (float*)(smem + SM_AHI) + row * 65 + col;
                    dst[0] = acc[m][n][2 * h + 0];
                    dst[1] = acc[m][n][2 * h + 1];
                }
            }
        __syncthreads();

        // Chebyshev contraction (threads 0..63, thread = point), cheb recomputed in regs
        if (tid < PTS) {
            float cp = *(float*)(smem + SM_CP + tid * 4);
            float ch[16];
            ch[0] = 1.0f; ch[1] = cp;
            #pragma unroll
            for (int o = 2; o < 16; o++) ch[o] = 2.0f * cp * ch[o - 1] - ch[o - 2];
            const float* cf = (float*)(smem + SM_AHI) + tid * 65;
            const int pt = blockIdx.x * PTS + tid;
            #pragma unroll
            for (int f = 0; f < 3; f++) {
                float sum = 0.0f;
                #pragma unroll
                for (int o = 0; o < 16; o++)
                    sum += (cf[f * 16 + o] + __ldg(bout + f * 16 + o)) * ch[o];
                out[pt * 3 + f] = sum;
            }
        }
    }
    #undef CHUNK_POST
}

// ---------------- launch ----------------
extern "C" void kernel_launch(void* const* d_in, const int* in_sizes, int n_in,
                              void* d_out, int out_size)
{
    const float* x      = (const float*)d_in[0];
    const float* view   = (const float*)d_in[1];
    const float* normal = (const float*)d_in[2];
    const float* light  = (const float*)d_in[3];
    const float* W0     = (const float*)d_in[4];
    const float* b0     = (const float*)d_in[5];
    const float* Wh     = (const float*)d_in[6];
    const float* bh     = (const float*)d_in[7];
    const float* Wout   = (const float*)d_in[8];
    const float* bout   = (const float*)d_in[9];
    float* out = (float*)d_out;

    convert_weights_kernel<<<544, 256>>>(W0, b0, Wh, bh, Wout);

    cudaFuncSetAttribute(fourier_mma_kernel,
                         cudaFuncAttributeMaxDynamicSharedMemorySize, (int)SM_TOTAL);
    fourier_mma_kernel<<<NBLK, TPB, SM_TOTAL>>>(x, view, normal, light, bout, out);
}

// round 13
// speedup vs baseline: 3.2309x; 2.5102x over previous
#include <cuda_runtime.h>
#include <cuda_bf16.h>
#include <cuda_fp16.h>
#include <math.h>
#include <stdint.h>

#define TPB   128
#define PTS   64
#define NBLK  4096

// ---------------- smem layout (bytes), per CTA (~48.3 KB -> 4 CTAs/SM) ----------------
#define SM_A    0u            // A fp16: 64 pts x 384B (192 f16: h[0..127], enc[128..190], bias)
#define SM_W0   24576u        // weight ring buffer 0 (12288B)
#define SM_W1   36864u        // weight ring buffer 1
#define SM_CP   49152u        // 64 x 4B cos_phi
#define SM_MBAR 49408u        // full0, full1, empty0, empty1
#define SM_TOTAL 49440u

// ---------------- global weight scratch (pre-swizzled fp16 smem images) ----------------
#define IMG_L0  0u
#define P_L0    16384u        // 64 rows x 256B
#define P_HID   49152u        // 192 rows x 256B
#define IMG_HID(l) (16384u + (uint32_t)((l) - 1) * 49152u)   // l = 1..5
#define IMG_OUT 262144u
#define P_OUT   16384u        // 128 rows x 128B (N padded to 64)
__device__ __align__(16) unsigned char g_wscratch[278528];

// chunk stream: 24 chunks total
//   id 0..1   : L0, 2 x 8192B  (32 rows each)
//   id 2..21  : hidden l=1..5, 4 x 12288B each (48 rows each)
//   id 22..23 : out, 2 x 8192B (64 rows each)
__device__ __forceinline__ const unsigned char* chunk_src(int id, uint32_t& sz) {
    if (id < 2)  { sz = 8192u;  return g_wscratch + IMG_L0 + (uint32_t)id * 8192u; }
    if (id < 22) { int t = id - 2; int l = t >> 2; int c = t & 3;
                   sz = 12288u; return g_wscratch + IMG_HID(l + 1) + (uint32_t)c * 12288u; }
    sz = 8192u; return g_wscratch + IMG_OUT + (uint32_t)(id - 22) * 8192u;
}

// ---------------- PTX helpers ----------------
__device__ __forceinline__ uint32_t smem_u32(const void* p) {
    uint32_t a;
    asm("{ .reg .u64 t; cvta.to.shared.u64 t, %1; cvt.u32.u64 %0, t; }" : "=r"(a) : "l"(p));
    return a;
}
__device__ __forceinline__ void ldsm_x4(uint32_t& r0, uint32_t& r1, uint32_t& r2, uint32_t& r3, uint32_t a) {
    asm volatile("ldmatrix.sync.aligned.m8n8.x4.shared.b16 {%0,%1,%2,%3}, [%4];"
        : "=r"(r0), "=r"(r1), "=r"(r2), "=r"(r3) : "r"(a));
}
__device__ __forceinline__ void ldsm_x4t(uint32_t& r0, uint32_t& r1, uint32_t& r2, uint32_t& r3, uint32_t a) {
    asm volatile("ldmatrix.sync.aligned.m8n8.x4.trans.shared.b16 {%0,%1,%2,%3}, [%4];"
        : "=r"(r0), "=r"(r1), "=r"(r2), "=r"(r3) : "r"(a));
}
__device__ __forceinline__ void mma_f16(float* d, uint32_t a0, uint32_t a1, uint32_t a2, uint32_t a3,
                                        uint32_t b0, uint32_t b1) {
    asm volatile("mma.sync.aligned.m16n8k16.row.col.f32.f16.f16.f32 "
        "{%0,%1,%2,%3}, {%4,%5,%6,%7}, {%8,%9}, {%0,%1,%2,%3};"
        : "+f"(d[0]), "+f"(d[1]), "+f"(d[2]), "+f"(d[3])
        : "r"(a0), "r"(a1), "r"(a2), "r"(a3), "r"(b0), "r"(b1));
}
#define MBARRIER_INIT(mb, c) asm volatile("mbarrier.init.shared.b64 [%0], %1;" :: "r"((uint32_t)(mb)), "r"((uint32_t)(c)) : "memory")
#define MBARRIER_ARRIVE(mb) asm volatile("mbarrier.arrive.shared.b64 _, [%0];" :: "r"((uint32_t)(mb)) : "memory")
#define MBAR_WAIT(mb, par) do {                                                     \
    uint32_t _mb = (uint32_t)(mb), _p = (uint32_t)(par);                            \
    asm volatile("{\n\t.reg .pred P1;\n\tWL_%=:\n\t"                                \
        "mbarrier.try_wait.parity.acquire.cta.shared::cta.b64 P1, [%0], %1, 0x989680;\n\t" \
        "@P1 bra.uni WD_%=;\n\tbra.uni WL_%=;\n\tWD_%=:\n\t}"                       \
        :: "r"(_mb), "r"(_p) : "memory");                                           \
} while (0)
// one-thread weight fetch: expect_tx + bulk async copy (zero warp issue cost)
__device__ __forceinline__ void w_fetch(uint32_t mb, uint32_t sdst, const unsigned char* gsrc, uint32_t bytes) {
    asm volatile("mbarrier.arrive.expect_tx.shared.b64 _, [%0], %1;"
        :: "r"(mb), "r"(bytes) : "memory");
    asm volatile("cp.async.bulk.shared::cluster.global.mbarrier::complete_tx::bytes [%0], [%1], %2, [%3];"
        :: "r"(sdst), "l"(gsrc), "r"(bytes), "r"(mb) : "memory");
}
__device__ __host__ __forceinline__ uint32_t swz_off(uint32_t row, uint32_t cb, uint32_t rowB) {
    return row * rowB + (cb & ~127u) + ((cb & 127u) ^ ((row & 7u) << 4));
}

// ---------------- weight converter: fp32 -> fp16 swizzled smem images ----------------
__global__ void convert_weights_kernel(const float* __restrict__ W0, const float* __restrict__ b0,
                                       const float* __restrict__ Wh, const float* __restrict__ bh,
                                       const float* __restrict__ Wout)
{
    int idx = blockIdx.x * blockDim.x + threadIdx.x;
    if (idx >= 139264) return;
    float w; uint32_t img, rowB, k, n;
    if (idx < 8192) {                       // L0: K=64 (row 63 = bias), N=128
        k = (uint32_t)(idx >> 7); n = (uint32_t)(idx & 127);
        img = IMG_L0; rowB = 256;
        w = (k < 63) ? W0[k * 128 + n] : b0[n];
    } else if (idx < 131072) {              // hidden: K=192 (row 191 = bias), N=128
        int t = idx - 8192; int l = t / 24576; int r = t % 24576;
        k = (uint32_t)(r >> 7); n = (uint32_t)(r & 127);
        img = IMG_HID(l + 1); rowB = 256;
        w = (k < 191) ? Wh[((uint32_t)l * 191 + k) * 128 + n] : bh[l * 128 + n];
    } else {                                // out: K=128, N=48 padded to 64
        int t = idx - 131072;
        k = (uint32_t)(t >> 6); n = (uint32_t)(t & 63);
        img = IMG_OUT; rowB = 128;
        w = (n < 48) ? Wout[k * 48 + n] : 0.0f;
    }
    uint32_t off = swz_off(k, n * 2, rowB);
    *(__half*)(g_wscratch + img + off) = __float2half_rn(w);
}

// ---------------- small math utils ----------------
__device__ __forceinline__ float3 norm3(float3 v, float eps) {
    float n = sqrtf(v.x * v.x + v.y * v.y + v.z * v.z);
    float inv = 1.0f / fmaxf(n, eps);
    return make_float3(v.x * inv, v.y * inv, v.z * inv);
}
__device__ __forceinline__ float3 cross3(float3 a, float3 b) {
    return make_float3(a.y * b.z - a.z * b.y, a.z * b.x - a.x * b.z, a.x * b.y - a.y * b.x);
}
__device__ __forceinline__ uint32_t packh(float a, float b) {
    __half2 p = __floats2half2_rn(a, b);
    return *(uint32_t*)&p;
}

// ---------------- MMA pass over one weight CHUNK (single fp16 pass) ----------------
template<int KSTEPS, int MT, int NT, int ROWB>
__device__ __forceinline__ void mma_pass(uint32_t sb, uint32_t wreg, int kbaseA,
                                         int m0, int n0, int lane, float (&acc)[MT][NT][4])
{
    const uint32_t l15 = (uint32_t)(lane & 15);
    const uint32_t lh  = (uint32_t)(lane >> 4);
    #pragma unroll
    for (int s = 0; s < KSTEPS; s++) {
        uint32_t b[NT][2];
        #pragma unroll
        for (int t = 0; t < NT / 2; t++) {
            uint32_t krow = (uint32_t)(16 * s) + l15;
            uint32_t cb = (uint32_t)(n0 * 2 + t * 32) + (lh << 4);
            uint32_t off = swz_off(krow, cb, (uint32_t)ROWB);
            ldsm_x4t(b[2 * t][0], b[2 * t][1], b[2 * t + 1][0], b[2 * t + 1][1], sb + wreg + off);
        }
        const uint32_t cbA = (uint32_t)((kbaseA + 16 * s) * 2) + (lh << 4);
        #pragma unroll
        for (int m = 0; m < MT; m++) {
            uint32_t row = (uint32_t)(m0 + 16 * m) + l15;
            uint32_t off = swz_off(row, cbA, 384u);
            uint32_t a0, a1, a2, a3;
            ldsm_x4(a0, a1, a2, a3, sb + SM_A + off);
            #pragma unroll
            for (int n = 0; n < NT; n++) mma_f16(acc[m][n], a0, a1, a2, a3, b[n][0], b[n][1]);
        }
    }
}

// hidden-layer epilogue: leaky-relu, fp16 pack, store into A h-region
__device__ __forceinline__ void epilogue_store(unsigned char* smem, float (&acc)[2][8][4],
                                               int lane, int m0, int n0)
{
    const int r  = lane >> 2;
    const int c2 = (lane & 3) * 2;
    #pragma unroll
    for (int m = 0; m < 2; m++)
        #pragma unroll
        for (int n = 0; n < 8; n++) {
            const uint32_t cb = (uint32_t)((n0 + 8 * n + c2) * 2);
            #pragma unroll
            for (int h = 0; h < 2; h++) {
                uint32_t row = (uint32_t)(m0 + 16 * m + r + 8 * h);
                float v0 = acc[m][n][2 * h + 0];
                float v1 = acc[m][n][2 * h + 1];
                v0 = v0 > 0.0f ? v0 : 0.01f * v0;
                v1 = v1 > 0.0f ? v1 : 0.01f * v1;
                uint32_t off = swz_off(row, cb, 384u);
                *(uint32_t*)(smem + SM_A + off) = packh(v0, v1);
            }
        }
}

// ---------------- main kernel ----------------
extern "C" __global__ void __launch_bounds__(TPB, 4)
fourier_mma_kernel(const float* __restrict__ x, const float* __restrict__ view,
                   const float* __restrict__ normal, const float* __restrict__ light,
                   const float* __restrict__ bout, float* __restrict__ out)
{
    extern __shared__ __align__(16) unsigned char smem[];
    const uint32_t sb = smem_u32(smem);
    const uint32_t mb0  = sb + SM_MBAR;        // full0
    const uint32_t mb1  = sb + SM_MBAR + 8;    // full1
    const uint32_t mbe0 = sb + SM_MBAR + 16;   // empty0 (count 4 = one arrive per warp)
    const uint32_t mbe1 = sb + SM_MBAR + 24;   // empty1
    const int tid  = threadIdx.x;
    const int lane = tid & 31;
    const int warp = tid >> 5;

    // init mbarriers + kick off first two chunk fetches
    if (tid == 0) {
        MBARRIER_INIT(mb0, 1);
        MBARRIER_INIT(mb1, 1);
        MBARRIER_INIT(mbe0, 4);
        MBARRIER_INIT(mbe1, 4);
        uint32_t s0, s1;
        const unsigned char* p0 = chunk_src(0, s0);
        const unsigned char* p1 = chunk_src(1, s1);
        w_fetch(mb0, sb + SM_W0, p0, s0);
        w_fetch(mb1, sb + SM_W1, p1, s1);
    }

    // ---- geometry + cos_phi + Fourier encoding (threads 0..63, thread = point) ----
    if (tid < PTS) {
        const int pt = blockIdx.x * PTS + tid;
        float3 xx = make_float3(x[pt * 3 + 0], x[pt * 3 + 1], x[pt * 3 + 2]);
        float3 vv = make_float3(view[pt * 3 + 0], view[pt * 3 + 1], view[pt * 3 + 2]);
        float3 nn = make_float3(normal[pt * 3 + 0], normal[pt * 3 + 1], normal[pt * 3 + 2]);
        float3 ll = make_float3(light[pt * 3 + 0], light[pt * 3 + 1], light[pt * 3 + 2]);

        float3 n = norm3(nn, 1e-6f);
        float sgn = (n.z >= 0.0f) ? 1.0f : -1.0f;
        float s_z = sgn + n.z;
        float safe = (fabsf(s_z) < 1e-6f) ? copysignf(1e-6f, s_z) : s_z;
        float a = -1.0f / safe;
        float b = n.x * n.y * a;
        float3 s = make_float3(n.x * n.x * a * sgn + 1.0f, b * sgn, -n.x * sgn);
        s = norm3(s, 1e-6f);
        float3 t = norm3(cross3(s, n), 1e-6f);
        s = norm3(cross3(n, t), 1e-6f);

        float3 v = norm3(vv, 1e-6f);
        float3 wo = norm3(make_float3(v.x * s.x + v.y * s.y + v.z * s.z,
                                      v.x * t.x + v.y * t.y + v.z * t.z,
                                      v.x * n.x + v.y * n.y + v.z * n.z), 1e-7f);
        float3 wi = norm3(make_float3(ll.x * s.x + ll.y * s.y + ll.z * s.z,
                                      ll.x * t.x + ll.y * t.y + ll.z * t.z,
                                      ll.x * n.x + ll.y * n.y + ll.z * n.z), 1e-7f);
        float num = -(wi.x * wo.x + wi.y * wo.y);
        float den = sqrtf((wo.x * wo.x + wo.y * wo.y) * (wi.x * wi.x + wi.y * wi.y));
        float cp = fminf(1.0f, fmaxf(-1.0f, num / den));
        *(float*)(smem + SM_CP + tid * 4) = cp;

        float enc[64];
        enc[0] = xx.x; enc[1] = xx.y; enc[2] = xx.z;
        float fr = 1.0f;
        #pragma unroll
        for (int f = 0; f < 10; f++) {
            float sv, cv;
            sincosf(xx.x * fr, &sv, &cv); enc[3 + f * 3 + 0] = sv; enc[33 + f * 3 + 0] = cv;
            sincosf(xx.y * fr, &sv, &cv); enc[3 + f * 3 + 1] = sv; enc[33 + f * 3 + 1] = cv;
            sincosf(xx.z * fr, &sv, &cv); enc[3 + f * 3 + 2] = sv; enc[33 + f * 3 + 2] = cv;
            fr *= 2.0f;
        }
        enc[63] = 1.0f;                      // bias slot

        #pragma unroll
        for (int j = 0; j < 32; j++) {
            uint32_t off = swz_off((uint32_t)tid, 256u + 4u * (uint32_t)j, 384u);
            *(uint32_t*)(smem + SM_A + off) = packh(enc[2 * j], enc[2 * j + 1]);
        }
    }
    __syncthreads();          // A/cp + mbarrier init visible
    uint32_t ph0 = 0, ph1 = 0;   // full-barrier phases (all threads)
    uint32_t pe0 = 0, pe1 = 0;   // empty-barrier phases (thread 0)
    int fid = 2;                 // next chunk to fetch

    // warp tiling: 2 m-groups (32 pts) x 2 n-groups
    const int mg = warp >> 1;
    const int ng = warp & 1;
    const int m0 = mg * 32;
    const int n0h = ng * 64;

    // per-chunk bookkeeping: arrive empty, thread0 waits empty then refills buffer
    #define CHUNK_POST(c)                                                            \
        if (lane == 0) MBARRIER_ARRIVE((c & 1) ? mbe1 : mbe0);                       \
        if (tid == 0 && fid < 24) {                                                  \
            if (c & 1) { MBAR_WAIT(mbe1, pe1); pe1 ^= 1; }                           \
            else       { MBAR_WAIT(mbe0, pe0); pe0 ^= 1; }                           \
            uint32_t s; const unsigned char* p = chunk_src(fid, s);                  \
            w_fetch((c & 1) ? mb1 : mb0, sb + ((c & 1) ? SM_W1 : SM_W0), p, s);      \
        }                                                                            \
        fid++;

    // ================= layer 0: chunks 0..1 (32 rows each) =================
    {
        float acc[2][8][4] = {};
        #pragma unroll
        for (int c = 0; c < 2; c++) {
            const uint32_t wreg = (c & 1) ? SM_W1 : SM_W0;
            if (c & 1) { MBAR_WAIT(mb1, ph1); ph1 ^= 1; } else { MBAR_WAIT(mb0, ph0); ph0 ^= 1; }
            mma_pass<2, 2, 8, 256>(sb, wreg, 128 + 32 * c, m0, n0h, lane, acc);
            CHUNK_POST(c)
        }
        // L0 reads enc-cols (bytes 256..383), epilogue writes h-cols (0..255): disjoint
        epilogue_store(smem, acc, lane, m0, n0h);
        __syncthreads();
    }

    // ================= hidden layers 1..5: 4 chunks each (48 rows) =================
    #pragma unroll 1
    for (int l = 1; l <= 5; l++) {
        float acc[2][8][4] = {};
        #pragma unroll
        for (int c = 0; c < 4; c++) {
            const uint32_t wreg = (c & 1) ? SM_W1 : SM_W0;
            if (c & 1) { MBAR_WAIT(mb1, ph1); ph1 ^= 1; } else { MBAR_WAIT(mb0, ph0); ph0 ^= 1; }
            mma_pass<3, 2, 8, 256>(sb, wreg, 48 * c, m0, n0h, lane, acc);
            CHUNK_POST(c)
        }
        __syncthreads();       // all warps done reading A(l) before overwrite
        epilogue_store(smem, acc, lane, m0, n0h);
        __syncthreads();       // A(l+1) visible
    }

    // ================= output layer: chunks 22..23 (64 rows each) =================
    {
        const int n0o = ng * 32;
        float acc[2][4][4] = {};
        #pragma unroll
        for (int c = 0; c < 2; c++) {
            const uint32_t wreg = (c & 1) ? SM_W1 : SM_W0;
            if (c & 1) { MBAR_WAIT(mb1, ph1); ph1 ^= 1; } else { MBAR_WAIT(mb0, ph0); ph0 ^= 1; }
            mma_pass<4, 2, 4, 128>(sb, wreg, 64 * c, m0, n0o, lane, acc);
            CHUNK_POST(c)
        }
        __syncthreads();       // all warps done with A + W buffers

        // stage coeffs into (now dead) A region: [pt][65 f32]
        const int r  = lane >> 2;
        const int c2 = (lane & 3) * 2;
        #pragma unroll
        for (int m = 0; m < 2; m++)
            #pragma unroll
            for (int n = 0; n < 4; n++) {
                int col = n0o + 8 * n + c2;
                #pragma unroll
                for (int h = 0; h < 2; h++) {
                    int row = m0 + 16 * m + r + 8 * h;
                    float* dst = (float*)(smem + SM_A) + row * 65 + col;
                    dst[0] = acc[m][n][2 * h + 0];
                    dst[1] = acc[m][n][2 * h + 1];
                }
            }
        __syncthreads();

        // Chebyshev contraction (threads 0..63, thread = point), cheb recomputed in regs
        if (tid < PTS) {
            float cp = *(float*)(smem + SM_CP + tid * 4);
            float ch[16];
            ch[0] = 1.0f; ch[1] = cp;
            #pragma unroll
            for (int o = 2; o < 16; o++) ch[o] = 2.0f * cp * ch[o - 1] - ch[o - 2];
            const float* cf = (float*)(smem + SM_A) + tid * 65;
            const int pt = blockIdx.x * PTS + tid;
            #pragma unroll
            for (int f = 0; f < 3; f++) {
                float sum = 0.0f;
                #pragma unroll
                for (int o = 0; o < 16; o++)
                    sum += (cf[f * 16 + o] + __ldg(bout + f * 16 + o)) * ch[o];
                out[pt * 3 + f] = sum;
            }
        }
    }
    #undef CHUNK_POST
}

// ---------------- launch ----------------
extern "C" void kernel_launch(void* const* d_in, const int* in_sizes, int n_in,
                              void* d_out, int out_size)
{
    const float* x      = (const float*)d_in[0];
    const float* view   = (const float*)d_in[1];
    const float* normal = (const float*)d_in[2];
    const float* light  = (const float*)d_in[3];
    const float* W0     = (const float*)d_in[4];
    const float* b0     = (const float*)d_in[5];
    const float* Wh     = (const float*)d_in[6];
    const float* bh     = (const float*)d_in[7];
    const float* Wout   = (const float*)d_in[8];
    const float* bout   = (const float*)d_in[9];
    float* out = (float*)d_out;

    convert_weights_kernel<<<544, 256>>>(W0, b0, Wh, bh, Wout);

    cudaFuncSetAttribute(fourier_mma_kernel,
                         cudaFuncAttributeMaxDynamicSharedMemorySize, (int)SM_TOTAL);
    fourier_mma_kernel<<<NBLK, TPB, SM_TOTAL>>>(x, view, normal, light, bout, out);
}